// round 11
// baseline (speedup 1.0000x reference)
#include <cuda_runtime.h>
#include <math.h>

#define T_STEPS 512
#define BATCH   256
#define OBS     128
#define LAT     64
#define HID     256
#define G3      (3*HID)      // 768
#define PIN     (HID+LAT)    // 320

// ---------------- scratch (device globals: allocation-free kernel_launch) ----
__device__ __align__(16) float g_gx[(size_t)T_STEPS*BATCH*G3];   // 384 MB
__device__ __align__(16) float g_hs[(size_t)T_STEPS*BATCH*HID];  // 128 MB
__device__ __align__(16) float g_whh_p[G3*HID];
__device__ __align__(16) float g_tw1_p[HID*LAT];
__device__ __align__(16) float g_tw2_p[2*LAT*HID];
__device__ __align__(16) float g_pw1_p[HID*PIN];
__device__ __align__(16) float g_pw2_p[2*LAT*HID];
__device__ __align__(16) float g_dw1_p[HID*LAT];
__device__ __align__(16) float g_dw2_p[OBS*HID];

// output section offsets (floats): recons | prior_mean | prior_logvar | post_mean | post_logvar
#define OFF_REC    0
#define OFF_PM     (T_STEPS*BATCH*OBS)
#define OFF_PLV    (OFF_PM  + T_STEPS*BATCH*LAT)
#define OFF_POSTM  (OFF_PLV + T_STEPS*BATCH*LAT)
#define OFF_POSTLV (OFF_POSTM + T_STEPS*BATCH*LAT)

// ---------------- f32x2 helpers ----------------------------------------------
__device__ __forceinline__ unsigned long long ffma2(unsigned long long a,
                                                    unsigned long long b,
                                                    unsigned long long c) {
    unsigned long long d;
    asm("fma.rn.f32x2 %0, %1, %2, %3;" : "=l"(d) : "l"(a), "l"(b), "l"(c));
    return d;
}
__device__ __forceinline__ float hsum2(unsigned long long v) {
    float lo, hi;
    asm("mov.b64 {%0, %1}, %2;" : "=f"(lo), "=f"(hi) : "l"(v));
    return lo + hi;
}
__device__ __forceinline__ float sigmoidf_(float x) { return 1.f / (1.f + expf(-x)); }

// ---------------- weight repack: [j][k] -> [(k/4)][j][k%4] -------------------
__device__ __forceinline__ void pack_seg(const float* __restrict__ s,
                                         float* __restrict__ d,
                                         int nout, int kin, int tid, int stride) {
    int total = nout * kin;
    for (int idx = tid; idx < total; idx += stride) {
        int j = idx / kin;
        int k = idx - j * kin;
        d[((k >> 2) * nout + j) * 4 + (k & 3)] = s[idx];
    }
}

__global__ void pack_all(const float* __restrict__ Whh, const float* __restrict__ tW1,
                         const float* __restrict__ tW2, const float* __restrict__ pW1,
                         const float* __restrict__ pW2, const float* __restrict__ dW1,
                         const float* __restrict__ dW2) {
    int tid = blockIdx.x * blockDim.x + threadIdx.x;
    int stride = gridDim.x * blockDim.x;
    pack_seg(Whh, g_whh_p, G3,    HID, tid, stride);
    pack_seg(tW1, g_tw1_p, HID,   LAT, tid, stride);
    pack_seg(tW2, g_tw2_p, 2*LAT, HID, tid, stride);
    pack_seg(pW1, g_pw1_p, HID,   PIN, tid, stride);
    pack_seg(pW2, g_pw2_p, 2*LAT, HID, tid, stride);
    pack_seg(dW1, g_dw1_p, HID,   LAT, tid, stride);
    pack_seg(dW2, g_dw2_p, OBS,   HID, tid, stride);
}

// ---------------- K1: gx = x @ W_ih^T + b_ih  ([131072,128] x [768,128]^T) ---
__global__ void __launch_bounds__(256) gx_kernel(const float* __restrict__ x,
                                                 const float* __restrict__ Wih,
                                                 const float* __restrict__ bih) {
    __shared__ float xs[64][68];
    __shared__ float ws[64][68];
    const int tid = threadIdx.x;
    const int ty = tid >> 4, tx = tid & 15;
    const int m0 = blockIdx.y * 64;
    const int n0 = blockIdx.x * 64;

    unsigned long long acc[4][4];
    #pragma unroll
    for (int i = 0; i < 4; i++)
        #pragma unroll
        for (int j = 0; j < 4; j++) acc[i][j] = 0ull;

    #pragma unroll
    for (int k0 = 0; k0 < OBS; k0 += 64) {
        #pragma unroll
        for (int p = 0; p < 4; p++) {
            int idx4 = tid + 256 * p;            // 1024 float4 per 64x64 tile
            int row = idx4 >> 4;
            int c   = (idx4 & 15) * 4;
            *(float4*)&xs[row][c] = *(const float4*)&x  [(size_t)(m0 + row) * OBS + k0 + c];
            *(float4*)&ws[row][c] = *(const float4*)&Wih[(size_t)(n0 + row) * OBS + k0 + c];
        }
        __syncthreads();
        #pragma unroll
        for (int k2 = 0; k2 < 32; k2++) {
            unsigned long long a[4], b[4];
            #pragma unroll
            for (int i = 0; i < 4; i++) a[i] = *(const unsigned long long*)&xs[ty + 16 * i][2 * k2];
            #pragma unroll
            for (int j = 0; j < 4; j++) b[j] = *(const unsigned long long*)&ws[tx + 16 * j][2 * k2];
            #pragma unroll
            for (int i = 0; i < 4; i++)
                #pragma unroll
                for (int j = 0; j < 4; j++) acc[i][j] = ffma2(a[i], b[j], acc[i][j]);
        }
        __syncthreads();
    }
    #pragma unroll
    for (int i = 0; i < 4; i++) {
        int m = m0 + ty + 16 * i;
        #pragma unroll
        for (int j = 0; j < 4; j++) {
            int n = n0 + tx + 16 * j;
            g_gx[(size_t)m * G3 + n] = hsum2(acc[i][j]) + bih[n];
        }
    }
}

// ---------------- K2: GRU scan. 64 CTAs x 4 batch rows, 256 threads ----------
__global__ void __launch_bounds__(256) gru_kernel(const float* __restrict__ bhh) {
    __shared__ float h_s[4][HID];
    const int i  = threadIdx.x;           // hidden index owned by this thread
    const int r0 = blockIdx.x * 4;        // first batch row of this CTA

    #pragma unroll
    for (int r = 0; r < 4; r++) h_s[r][i] = 0.f;

    const float bh_r = bhh[i];
    const float bh_z = bhh[HID + i];
    const float bh_n = bhh[2 * HID + i];
    const ulonglong2* __restrict__ wp = (const ulonglong2*)g_whh_p;
    __syncthreads();

    for (int t = 0; t < T_STEPS; t++) {
        unsigned long long ar[4] = {0,0,0,0}, az[4] = {0,0,0,0}, an[4] = {0,0,0,0};
        #pragma unroll 4
        for (int k4 = 0; k4 < HID / 4; k4++) {
            ulonglong2 wr = wp[k4 * G3 + i];
            ulonglong2 wz = wp[k4 * G3 + HID + i];
            ulonglong2 wn = wp[k4 * G3 + 2 * HID + i];
            #pragma unroll
            for (int r = 0; r < 4; r++) {
                ulonglong2 hv = *(const ulonglong2*)&h_s[r][k4 * 4];
                ar[r] = ffma2(hv.x, wr.x, ar[r]); ar[r] = ffma2(hv.y, wr.y, ar[r]);
                az[r] = ffma2(hv.x, wz.x, az[r]); az[r] = ffma2(hv.y, wz.y, az[r]);
                an[r] = ffma2(hv.x, wn.x, an[r]); an[r] = ffma2(hv.y, wn.y, an[r]);
            }
        }
        __syncthreads();   // all reads of h(t-1) done
        const size_t gbase = ((size_t)t * BATCH + r0) * G3;
        #pragma unroll
        for (int r = 0; r < 4; r++) {
            const float* gxr = g_gx + gbase + (size_t)r * G3;
            float xr = gxr[i], xz = gxr[HID + i], xn = gxr[2 * HID + i];
            float hr = hsum2(ar[r]) + bh_r;
            float hz = hsum2(az[r]) + bh_z;
            float hn = hsum2(an[r]) + bh_n;
            float rg = sigmoidf_(xr + hr);
            float zg = sigmoidf_(xz + hz);
            float ng = tanhf(xn + rg * hn);
            float hnew = (1.f - zg) * ng + zg * h_s[r][i];
            h_s[r][i] = hnew;
            g_hs[((size_t)t * BATCH + r0 + r) * HID + i] = hnew;
        }
        __syncthreads();   // h(t) visible before next step's reads
    }
}

// ---------------- K3: prior/posterior/decoder scan ---------------------------
__global__ void __launch_bounds__(256) vrnn_kernel(
        const float* __restrict__ eps,
        const float* __restrict__ tb1, const float* __restrict__ tb2,
        const float* __restrict__ pb1, const float* __restrict__ pb2,
        const float* __restrict__ db1, const float* __restrict__ db2,
        float* __restrict__ out) {
    __shared__ float pin_s[4][PIN];      // [h(0..255) | z(256..319)]
    __shared__ float a1_s[4][HID];       // prior hidden; reused for decoder hidden
    __shared__ float a2_s[4][HID];       // posterior hidden
    __shared__ float post_s[4][2 * LAT];

    const int tid = threadIdx.x;
    const int r0  = blockIdx.x * 4;
    const int jj  = tid & 127;
    const bool isPost = (tid >= 128);

    { int r = tid >> 6, l = tid & 63; pin_s[r][HID + l] = 0.f; }   // z0 = 0

    const float tb1_j = tb1[tid];
    const float pb1_j = pb1[tid];
    const float db1_j = db1[tid];
    const float bB    = isPost ? pb2[jj] : tb2[jj];
    const float db2_j = db2[jj];

    const ulonglong2* __restrict__ tw1p = (const ulonglong2*)g_tw1_p;
    const ulonglong2* __restrict__ pw1p = (const ulonglong2*)g_pw1_p;
    const ulonglong2* __restrict__ dw1p = (const ulonglong2*)g_dw1_p;
    const ulonglong2* __restrict__ dw2p = (const ulonglong2*)g_dw2_p;
    const ulonglong2* __restrict__ w2p  = isPost ? (const ulonglong2*)g_pw2_p
                                                 : (const ulonglong2*)g_tw2_p;
    __syncthreads();

    for (int t = 0; t < T_STEPS; t++) {
        // ---- copy h_t into pin (z_prev already resident)
        {
            size_t base = ((size_t)t * BATCH + r0) * HID;
            #pragma unroll
            for (int q = 0; q < 4; q++) {
                int idx = tid + q * 256;
                int r = idx >> 8, c = idx & 255;
                pin_s[r][c] = g_hs[base + (size_t)r * HID + c];
            }
        }
        __syncthreads();   // S1

        // ---- Stage A: prior hidden a1 = relu(tW1 @ z_prev + tb1)   (K=64)
        {
            unsigned long long acc[4] = {0,0,0,0};
            #pragma unroll
            for (int k4 = 0; k4 < LAT / 4; k4++) {
                ulonglong2 w = tw1p[k4 * HID + tid];
                #pragma unroll
                for (int r = 0; r < 4; r++) {
                    ulonglong2 av = *(const ulonglong2*)&pin_s[r][HID + k4 * 4];
                    acc[r] = ffma2(av.x, w.x, acc[r]); acc[r] = ffma2(av.y, w.y, acc[r]);
                }
            }
            #pragma unroll
            for (int r = 0; r < 4; r++) a1_s[r][tid] = fmaxf(hsum2(acc[r]) + tb1_j, 0.f);
        }
        // ---- Stage A2: posterior hidden a2 = relu(pW1 @ [h;z] + pb1)  (K=320)
        {
            unsigned long long acc[4] = {0,0,0,0};
            #pragma unroll 4
            for (int k4 = 0; k4 < PIN / 4; k4++) {
                ulonglong2 w = pw1p[k4 * HID + tid];
                #pragma unroll
                for (int r = 0; r < 4; r++) {
                    ulonglong2 av = *(const ulonglong2*)&pin_s[r][k4 * 4];
                    acc[r] = ffma2(av.x, w.x, acc[r]); acc[r] = ffma2(av.y, w.y, acc[r]);
                }
            }
            #pragma unroll
            for (int r = 0; r < 4; r++) a2_s[r][tid] = fmaxf(hsum2(acc[r]) + pb1_j, 0.f);
        }
        __syncthreads();   // S2

        // ---- Stage B: threads 0..127 prior head, 128..255 posterior head  (K=256)
        {
            const float* asrc = isPost ? &a2_s[0][0] : &a1_s[0][0];
            unsigned long long acc[4] = {0,0,0,0};
            #pragma unroll 4
            for (int k4 = 0; k4 < HID / 4; k4++) {
                ulonglong2 w = w2p[k4 * 128 + jj];
                #pragma unroll
                for (int r = 0; r < 4; r++) {
                    ulonglong2 av = *(const ulonglong2*)(asrc + r * HID + k4 * 4);
                    acc[r] = ffma2(av.x, w.x, acc[r]); acc[r] = ffma2(av.y, w.y, acc[r]);
                }
            }
            int tb = t * BATCH + r0;
            #pragma unroll
            for (int r = 0; r < 4; r++) {
                float v = hsum2(acc[r]) + bB;
                size_t orow = (size_t)(tb + r) * LAT;
                if (isPost) {
                    post_s[r][jj] = v;
                    if (jj < 64) out[OFF_POSTM  + orow + jj]      = v;
                    else         out[OFF_POSTLV + orow + jj - 64] = v;
                } else {
                    if (jj < 64) out[OFF_PM  + orow + jj]      = v;
                    else         out[OFF_PLV + orow + jj - 64] = v;
                }
            }
        }
        __syncthreads();   // S3

        // ---- z update: z = post_mean + eps * exp(0.5*post_logvar)
        {
            int r = tid >> 6, l = tid & 63;
            float pm  = post_s[r][l];
            float plv = post_s[r][LAT + l];
            float e   = eps[((size_t)t * BATCH + r0 + r) * LAT + l];
            pin_s[r][HID + l] = pm + e * expf(0.5f * plv);
        }
        __syncthreads();   // S4

        // ---- Stage C: decoder hidden a3 = relu(dW1 @ z_t + db1) (K=64), into a1_s
        {
            unsigned long long acc[4] = {0,0,0,0};
            #pragma unroll
            for (int k4 = 0; k4 < LAT / 4; k4++) {
                ulonglong2 w = dw1p[k4 * HID + tid];
                #pragma unroll
                for (int r = 0; r < 4; r++) {
                    ulonglong2 av = *(const ulonglong2*)&pin_s[r][HID + k4 * 4];
                    acc[r] = ffma2(av.x, w.x, acc[r]); acc[r] = ffma2(av.y, w.y, acc[r]);
                }
            }
            #pragma unroll
            for (int r = 0; r < 4; r++) a1_s[r][tid] = fmaxf(hsum2(acc[r]) + db1_j, 0.f);
        }
        __syncthreads();   // S5

        // ---- Stage D: recon = dW2 @ a3 + db2  (128 outs x 4 rows; 2 rows/thread)
        {
            int rb = (tid >> 7) * 2;     // rows {0,1} or {2,3}
            unsigned long long acc[2] = {0,0};
            #pragma unroll 4
            for (int k4 = 0; k4 < HID / 4; k4++) {
                ulonglong2 w = dw2p[k4 * 128 + jj];
                #pragma unroll
                for (int rr = 0; rr < 2; rr++) {
                    ulonglong2 av = *(const ulonglong2*)&a1_s[rb + rr][k4 * 4];
                    acc[rr] = ffma2(av.x, w.x, acc[rr]); acc[rr] = ffma2(av.y, w.y, acc[rr]);
                }
            }
            #pragma unroll
            for (int rr = 0; rr < 2; rr++) {
                size_t orow = ((size_t)t * BATCH + r0 + rb + rr) * OBS;
                out[OFF_REC + orow + jj] = hsum2(acc[rr]) + db2_j;
            }
        }
        __syncthreads();   // S6 (protects a1_s/pin before next-iter writes)
    }
}

// ---------------- host launch -------------------------------------------------
extern "C" void kernel_launch(void* const* d_in, const int* in_sizes, int n_in,
                              void* d_out, int out_size) {
    const float* x   = (const float*)d_in[0];
    const float* eps = (const float*)d_in[1];
    const float* Wih = (const float*)d_in[2];
    const float* Whh = (const float*)d_in[3];
    const float* bih = (const float*)d_in[4];
    const float* bhh = (const float*)d_in[5];
    const float* tW1 = (const float*)d_in[6];
    const float* tb1 = (const float*)d_in[7];
    const float* tW2 = (const float*)d_in[8];
    const float* tb2 = (const float*)d_in[9];
    const float* pW1 = (const float*)d_in[10];
    const float* pb1 = (const float*)d_in[11];
    const float* pW2 = (const float*)d_in[12];
    const float* pb2 = (const float*)d_in[13];
    const float* dW1 = (const float*)d_in[14];
    const float* db1 = (const float*)d_in[15];
    const float* dW2 = (const float*)d_in[16];
    const float* db2 = (const float*)d_in[17];
    float* out = (float*)d_out;

    pack_all<<<148, 256>>>(Whh, tW1, tW2, pW1, pW2, dW1, dW2);

    dim3 g1(G3 / 64, (T_STEPS * BATCH) / 64);
    gx_kernel<<<g1, 256>>>(x, Wih, bih);

    gru_kernel<<<64, 256>>>(bhh);

    vrnn_kernel<<<64, 256>>>(eps, tb1, tb2, pb1, pb2, db1, db2, out);
}

// round 12
// speedup vs baseline: 2.0639x; 2.0639x over previous
#include <cuda_runtime.h>
#include <math.h>

#define T_STEPS 512
#define BATCH   256
#define OBS     128
#define LAT     64
#define HID     256
#define G3      (3*HID)      // 768
#define PIN     (HID+LAT)    // 320

// ---------------- scratch (device globals: allocation-free kernel_launch) ----
__device__ __align__(16) float g_gx[(size_t)T_STEPS*BATCH*G3];   // 384 MB
__device__ __align__(16) float g_hs[(size_t)T_STEPS*BATCH*HID];  // 128 MB
__device__ __align__(16) float g_tw1_p[HID*LAT];
__device__ __align__(16) float g_tw2_p[2*LAT*HID];
__device__ __align__(16) float g_pw1_p[HID*PIN];
__device__ __align__(16) float g_pw2_p[2*LAT*HID];
__device__ __align__(16) float g_dw1_p[HID*LAT];
__device__ __align__(16) float g_dw2_p[OBS*HID];

// output offsets (floats): recons | prior_mean | prior_logvar | post_mean | post_logvar
#define OFF_REC    0
#define OFF_PM     ((size_t)T_STEPS*BATCH*OBS)
#define OFF_PLV    (OFF_PM  + (size_t)T_STEPS*BATCH*LAT)
#define OFF_POSTM  (OFF_PLV + (size_t)T_STEPS*BATCH*LAT)
#define OFF_POSTLV (OFF_POSTM + (size_t)T_STEPS*BATCH*LAT)

// ---------------- helpers ----------------------------------------------------
__device__ __forceinline__ unsigned long long ffma2(unsigned long long a,
                                                    unsigned long long b,
                                                    unsigned long long c) {
    unsigned long long d;
    asm("fma.rn.f32x2 %0, %1, %2, %3;" : "=l"(d) : "l"(a), "l"(b), "l"(c));
    return d;
}
__device__ __forceinline__ float hsum2(unsigned long long v) {
    float lo, hi;
    asm("mov.b64 {%0, %1}, %2;" : "=f"(lo), "=f"(hi) : "l"(v));
    return lo + hi;
}
__device__ __forceinline__ float sigmoidf_(float x) { return 1.f / (1.f + expf(-x)); }

__device__ __forceinline__ unsigned smem_u32(const void* p) {
    unsigned a;
    asm("{ .reg .u64 t; cvta.to.shared.u64 t, %1; cvt.u32.u64 %0, t; }" : "=r"(a) : "l"(p));
    return a;
}
__device__ __forceinline__ void st_cluster_f32(unsigned addr, unsigned rank, float v) {
    asm volatile("{ .reg .b32 ra; mapa.shared::cluster.u32 ra, %0, %1; "
                 "st.shared::cluster.f32 [ra], %2; }"
                 :: "r"(addr), "r"(rank), "f"(v) : "memory");
}
__device__ __forceinline__ void cluster_sync_() {
    asm volatile("barrier.cluster.arrive.aligned;" ::: "memory");
    asm volatile("barrier.cluster.wait.aligned;" ::: "memory");
}

// ---------------- weight repack (vrnn only): [j][k] -> [(k/4)][j][k%4] -------
__device__ __forceinline__ void pack_seg(const float* __restrict__ s,
                                         float* __restrict__ d,
                                         int nout, int kin, int tid, int stride) {
    int total = nout * kin;
    for (int idx = tid; idx < total; idx += stride) {
        int j = idx / kin;
        int k = idx - j * kin;
        d[((k >> 2) * nout + j) * 4 + (k & 3)] = s[idx];
    }
}

__global__ void pack_all(const float* __restrict__ tW1, const float* __restrict__ tW2,
                         const float* __restrict__ pW1, const float* __restrict__ pW2,
                         const float* __restrict__ dW1, const float* __restrict__ dW2) {
    int tid = blockIdx.x * blockDim.x + threadIdx.x;
    int stride = gridDim.x * blockDim.x;
    pack_seg(tW1, g_tw1_p, HID,   LAT, tid, stride);
    pack_seg(tW2, g_tw2_p, 2*LAT, HID, tid, stride);
    pack_seg(pW1, g_pw1_p, HID,   PIN, tid, stride);
    pack_seg(pW2, g_pw2_p, 2*LAT, HID, tid, stride);
    pack_seg(dW1, g_dw1_p, HID,   LAT, tid, stride);
    pack_seg(dW2, g_dw2_p, OBS,   HID, tid, stride);
}

// ---------------- K1: gx = x @ W_ih^T + b_ih ---------------------------------
__global__ void __launch_bounds__(256) gx_kernel(const float* __restrict__ x,
                                                 const float* __restrict__ Wih,
                                                 const float* __restrict__ bih) {
    __shared__ float xs[64][68];
    __shared__ float wsm[64][68];
    const int tid = threadIdx.x;
    const int ty = tid >> 4, tx = tid & 15;
    const int m0 = blockIdx.y * 64;
    const int n0 = blockIdx.x * 64;

    unsigned long long acc[4][4];
    #pragma unroll
    for (int i = 0; i < 4; i++)
        #pragma unroll
        for (int j = 0; j < 4; j++) acc[i][j] = 0ull;

    #pragma unroll
    for (int k0 = 0; k0 < OBS; k0 += 64) {
        #pragma unroll
        for (int p = 0; p < 4; p++) {
            int idx4 = tid + 256 * p;
            int row = idx4 >> 4;
            int c   = (idx4 & 15) * 4;
            *(float4*)&xs [row][c] = *(const float4*)&x  [(size_t)(m0 + row) * OBS + k0 + c];
            *(float4*)&wsm[row][c] = *(const float4*)&Wih[(size_t)(n0 + row) * OBS + k0 + c];
        }
        __syncthreads();
        #pragma unroll
        for (int k2 = 0; k2 < 32; k2++) {
            unsigned long long a[4], b[4];
            #pragma unroll
            for (int i = 0; i < 4; i++) a[i] = *(const unsigned long long*)&xs [ty + 16 * i][2 * k2];
            #pragma unroll
            for (int j = 0; j < 4; j++) b[j] = *(const unsigned long long*)&wsm[tx + 16 * j][2 * k2];
            #pragma unroll
            for (int i = 0; i < 4; i++)
                #pragma unroll
                for (int j = 0; j < 4; j++) acc[i][j] = ffma2(a[i], b[j], acc[i][j]);
        }
        __syncthreads();
    }
    #pragma unroll
    for (int i = 0; i < 4; i++) {
        int m = m0 + ty + 16 * i;
        #pragma unroll
        for (int j = 0; j < 4; j++) {
            int n = n0 + tx + 16 * j;
            g_gx[(size_t)m * G3 + n] = hsum2(acc[i][j]) + bih[n];
        }
    }
}

// ---------------- K2: GRU scan, 4-CTA clusters, weights SMEM-resident --------
// Cluster = 8 batch rows. CTA rank c owns hidden indices [64c, 64c+64) (192 gate
// rows). h double-buffered in SMEM, exchanged via DSMEM, 1 cluster.sync/step.
#define GRU_WS_FLOATS (64*192*4)                 // 49152: ws[k4][192][4]
#define GRU_H_FLOATS  (2*8*256)                  // 4096
#define GRU_GH_FLOATS (192*9)                    // 1728 (pitch 9: conflict-free)
#define GRU_SMEM_BYTES ((GRU_WS_FLOATS + GRU_H_FLOATS + 2*GRU_GH_FLOATS)*4)  // 226816

__global__ void __launch_bounds__(384, 1) __cluster_dims__(4, 1, 1)
gru_cluster_kernel(const float* __restrict__ Whh, const float* __restrict__ bhh) {
    extern __shared__ float sm[];
    float* ws   = sm;                      // weights [k4][192 l][4]
    float* hbuf = ws + GRU_WS_FLOATS;      // [2][8][256]
    float* gh   = hbuf + GRU_H_FLOATS;     // [192][9]
    float* part = gh + GRU_GH_FLOATS;      // [192][9]

    unsigned rank; asm("mov.u32 %0, %%cluster_ctarank;" : "=r"(rank));
    const int tid = threadIdx.x;
    const int r0  = (blockIdx.x >> 2) * 8;        // first batch row of this cluster

    // one-time load of this CTA's 192 gate rows of W_hh, layout [k4][l][4]
    for (int idx = tid; idx < 192 * 64; idx += 384) {
        int k4 = idx / 192, l = idx - k4 * 192;
        int g = l >> 6, il = l & 63;
        int j = g * 256 + (int)rank * 64 + il;
        *(float4*)&ws[(size_t)idx * 4] = *(const float4*)&Whh[(size_t)j * 256 + k4 * 4];
    }
    for (int idx = tid; idx < GRU_H_FLOATS; idx += 384) hbuf[idx] = 0.f;

    const int l  = tid % 192;       // gate row for GEMV
    const int kh = tid / 192;       // k-half 0/1
    {   // bias handled only by kh==0 thread of each row
    }
    const int gg = l >> 6, il = l & 63;
    const float bias = bhh[gg * 256 + (int)rank * 64 + il];
    const unsigned hbuf_u32 = smem_u32(hbuf);

    __syncthreads();
    cluster_sync_();                 // peers' h init must complete before step-0 writes

    int buf = 0;
    for (int t = 0; t < T_STEPS; t++) {
        // prefetch gx for pointwise (consumed ~4K cycles later)
        float gxv[2][3];
        if (tid < 256) {
            #pragma unroll
            for (int q = 0; q < 2; q++) {
                int item = tid + q * 256;
                int r = item >> 6, il2 = item & 63;
                size_t base = ((size_t)t * BATCH + r0 + r) * G3 + rank * 64 + il2;
                gxv[q][0] = g_gx[base];
                gxv[q][1] = g_gx[base + 256];
                gxv[q][2] = g_gx[base + 512];
            }
        }
        // GEMV: gh[l][r] = sum_k W[l][k] * h[r][k]   (this thread: k-half kh)
        unsigned long long acc[8] = {0,0,0,0,0,0,0,0};
        const float* hb = hbuf + buf * 2048 + kh * 128;
        #pragma unroll 4
        for (int kk = 0; kk < 32; kk++) {
            int k4 = kh * 32 + kk;
            ulonglong2 w = *(const ulonglong2*)&ws[(k4 * 192 + l) * 4];
            #pragma unroll
            for (int r = 0; r < 8; r++) {
                ulonglong2 hv = *(const ulonglong2*)&hb[r * 256 + kk * 4];
                acc[r] = ffma2(hv.x, w.x, acc[r]);
                acc[r] = ffma2(hv.y, w.y, acc[r]);
            }
        }
        if (kh == 1) {
            #pragma unroll
            for (int r = 0; r < 8; r++) part[l * 9 + r] = hsum2(acc[r]);
        }
        __syncthreads();
        if (kh == 0) {
            #pragma unroll
            for (int r = 0; r < 8; r++) gh[l * 9 + r] = hsum2(acc[r]) + part[l * 9 + r] + bias;
        }
        __syncthreads();
        // pointwise + exchange: each of 256 threads handles 2 (r, il2) items
        if (tid < 256) {
            #pragma unroll
            for (int q = 0; q < 2; q++) {
                int item = tid + q * 256;
                int r = item >> 6, il2 = item & 63;
                float hr_ = gh[(il2)        * 9 + r];
                float hz_ = gh[(64  + il2)  * 9 + r];
                float hn_ = gh[(128 + il2)  * 9 + r];
                float rg = sigmoidf_(gxv[q][0] + hr_);
                float zg = sigmoidf_(gxv[q][1] + hz_);
                float ng = tanhf(gxv[q][2] + rg * hn_);
                float hold = hbuf[buf * 2048 + r * 256 + rank * 64 + il2];
                float hnew = (1.f - zg) * ng + zg * hold;
                unsigned off = (unsigned)(((buf ^ 1) * 2048 + r * 256 + (int)rank * 64 + il2) * 4);
                #pragma unroll
                for (int pr = 0; pr < 4; pr++) st_cluster_f32(hbuf_u32 + off, (unsigned)pr, hnew);
                g_hs[((size_t)t * BATCH + r0 + r) * HID + rank * 64 + il2] = hnew;
            }
        }
        cluster_sync_();
        buf ^= 1;
    }
}

// ---------------- K3: prior/posterior/decoder scan, 512 threads, split-K -----
__global__ void __launch_bounds__(512) vrnn_kernel(
        const float* __restrict__ eps,
        const float* __restrict__ tb1, const float* __restrict__ tb2,
        const float* __restrict__ pb1, const float* __restrict__ pb2,
        const float* __restrict__ db1, const float* __restrict__ db2,
        float* __restrict__ out) {
    __shared__ float pin_s[4][PIN];      // [h | z]
    __shared__ float a1_s[4][HID];       // prior hidden; reused for decoder hidden
    __shared__ float a2_s[4][HID];       // posterior hidden
    __shared__ float post_s[4][2 * LAT];
    __shared__ float partA[256 * 5];     // pitch-5: conflict-free
    __shared__ float partB[256 * 5];
    __shared__ float partD[3][128 * 5];

    const int tid = threadIdx.x;
    const int r0  = blockIdx.x * 4;
    const int j2  = tid & 255;           // out index for 256-wide stages
    const int s2  = tid >> 8;            // split-2 id
    const int jj  = tid & 127;           // out index for 128-wide stages
    const int head = (tid >> 7) & 1;     // stage B: 0=prior, 1=post
    const int sD  = tid >> 7;            // stage D split-4 id

    { int r = tid >> 7, lz = tid & 127; if (lz < 64) pin_s[r][HID + lz] = 0.f; }

    const float tb1_j = tb1[j2];
    const float pb1_j = pb1[j2];
    const float db1_j = db1[j2];
    const float bB    = head ? pb2[jj] : tb2[jj];
    const float db2_j = db2[jj];

    const ulonglong2* __restrict__ tw1p = (const ulonglong2*)g_tw1_p;
    const ulonglong2* __restrict__ pw1p = (const ulonglong2*)g_pw1_p;
    const ulonglong2* __restrict__ dw1p = (const ulonglong2*)g_dw1_p;
    const ulonglong2* __restrict__ dw2p = (const ulonglong2*)g_dw2_p;
    const ulonglong2* __restrict__ w2p  = head ? (const ulonglong2*)g_pw2_p
                                               : (const ulonglong2*)g_tw2_p;
    const float* asrc = head ? &a2_s[0][0] : &a1_s[0][0];
    __syncthreads();

    for (int t = 0; t < T_STEPS; t++) {
        // prefetch eps for z-update
        float epv = 0.f;
        if (tid < 256)
            epv = eps[((size_t)t * BATCH + r0 + (tid >> 6)) * LAT + (tid & 63)];

        // copy h_t into pin (z_prev already resident)
        {
            size_t base = ((size_t)t * BATCH + r0) * HID;
            #pragma unroll
            for (int q = 0; q < 2; q++) {
                int idx = tid + q * 512;
                int r = idx >> 8, c = idx & 255;
                pin_s[r][c] = g_hs[base + (size_t)r * HID + c];
            }
        }
        __syncthreads();   // S1

        // ---- Stage A (prior hidden, K=64, split 2) + A2 (post hidden, K=320, split 2)
        float ownA[4], ownA2[4];
        {
            unsigned long long acc[4] = {0,0,0,0};
            #pragma unroll
            for (int kk = 0; kk < 8; kk++) {
                int k4 = s2 * 8 + kk;
                ulonglong2 w = tw1p[k4 * HID + j2];
                #pragma unroll
                for (int r = 0; r < 4; r++) {
                    ulonglong2 av = *(const ulonglong2*)&pin_s[r][HID + k4 * 4];
                    acc[r] = ffma2(av.x, w.x, acc[r]); acc[r] = ffma2(av.y, w.y, acc[r]);
                }
            }
            #pragma unroll
            for (int r = 0; r < 4; r++) ownA[r] = hsum2(acc[r]);
        }
        {
            unsigned long long acc[4] = {0,0,0,0};
            #pragma unroll 4
            for (int kk = 0; kk < 40; kk++) {
                int k4 = s2 * 40 + kk;
                ulonglong2 w = pw1p[k4 * HID + j2];
                #pragma unroll
                for (int r = 0; r < 4; r++) {
                    ulonglong2 av = *(const ulonglong2*)&pin_s[r][k4 * 4];
                    acc[r] = ffma2(av.x, w.x, acc[r]); acc[r] = ffma2(av.y, w.y, acc[r]);
                }
            }
            #pragma unroll
            for (int r = 0; r < 4; r++) ownA2[r] = hsum2(acc[r]);
        }
        if (s2) {
            #pragma unroll
            for (int r = 0; r < 4; r++) { partA[j2 * 5 + r] = ownA[r]; partB[j2 * 5 + r] = ownA2[r]; }
        }
        __syncthreads();   // S2
        if (!s2) {
            #pragma unroll
            for (int r = 0; r < 4; r++) {
                a1_s[r][j2] = fmaxf(ownA[r]  + partA[j2 * 5 + r] + tb1_j, 0.f);
                a2_s[r][j2] = fmaxf(ownA2[r] + partB[j2 * 5 + r] + pb1_j, 0.f);
            }
        }
        __syncthreads();   // S3

        // ---- Stage B: heads (prior|post), K=256, split 2
        {
            unsigned long long acc[4] = {0,0,0,0};
            #pragma unroll 4
            for (int kk = 0; kk < 32; kk++) {
                int k4 = s2 * 32 + kk;
                ulonglong2 w = w2p[k4 * 128 + jj];
                #pragma unroll
                for (int r = 0; r < 4; r++) {
                    ulonglong2 av = *(const ulonglong2*)(asrc + r * HID + k4 * 4);
                    acc[r] = ffma2(av.x, w.x, acc[r]); acc[r] = ffma2(av.y, w.y, acc[r]);
                }
            }
            if (s2) {
                #pragma unroll
                for (int r = 0; r < 4; r++) partA[(head * 128 + jj) * 5 + r] = hsum2(acc[r]);
            }
            __syncthreads();   // S4
            if (!s2) {
                int tb = t * BATCH + r0;
                #pragma unroll
                for (int r = 0; r < 4; r++) {
                    float v = hsum2(acc[r]) + partA[(head * 128 + jj) * 5 + r] + bB;
                    size_t orow = (size_t)(tb + r) * LAT;
                    if (head) {
                        post_s[r][jj] = v;
                        if (jj < 64) out[OFF_POSTM  + orow + jj]      = v;
                        else         out[OFF_POSTLV + orow + jj - 64] = v;
                    } else {
                        if (jj < 64) out[OFF_PM  + orow + jj]      = v;
                        else         out[OFF_PLV + orow + jj - 64] = v;
                    }
                }
            }
        }
        __syncthreads();   // S5

        // ---- z update
        if (tid < 256) {
            int r = tid >> 6, lz = tid & 63;
            float pm  = post_s[r][lz];
            float plv = post_s[r][LAT + lz];
            pin_s[r][HID + lz] = pm + epv * expf(0.5f * plv);
        }
        __syncthreads();   // S6

        // ---- Stage C: decoder hidden (K=64, split 2) -> a1_s
        {
            unsigned long long acc[4] = {0,0,0,0};
            #pragma unroll
            for (int kk = 0; kk < 8; kk++) {
                int k4 = s2 * 8 + kk;
                ulonglong2 w = dw1p[k4 * HID + j2];
                #pragma unroll
                for (int r = 0; r < 4; r++) {
                    ulonglong2 av = *(const ulonglong2*)&pin_s[r][HID + k4 * 4];
                    acc[r] = ffma2(av.x, w.x, acc[r]); acc[r] = ffma2(av.y, w.y, acc[r]);
                }
            }
            if (s2) {
                #pragma unroll
                for (int r = 0; r < 4; r++) partB[j2 * 5 + r] = hsum2(acc[r]);
            }
            __syncthreads();   // S7
            if (!s2) {
                #pragma unroll
                for (int r = 0; r < 4; r++)
                    a1_s[r][j2] = fmaxf(hsum2(acc[r]) + partB[j2 * 5 + r] + db1_j, 0.f);
            }
        }
        __syncthreads();   // S8

        // ---- Stage D: recon (128 outs, K=256, split 4)
        {
            unsigned long long acc[4] = {0,0,0,0};
            #pragma unroll 4
            for (int kk = 0; kk < 16; kk++) {
                int k4 = sD * 16 + kk;
                ulonglong2 w = dw2p[k4 * 128 + jj];
                #pragma unroll
                for (int r = 0; r < 4; r++) {
                    ulonglong2 av = *(const ulonglong2*)&a1_s[r][k4 * 4];
                    acc[r] = ffma2(av.x, w.x, acc[r]); acc[r] = ffma2(av.y, w.y, acc[r]);
                }
            }
            if (sD) {
                #pragma unroll
                for (int r = 0; r < 4; r++) partD[sD - 1][jj * 5 + r] = hsum2(acc[r]);
            }
            __syncthreads();   // S9
            if (sD == 0) {
                #pragma unroll
                for (int r = 0; r < 4; r++) {
                    float v = hsum2(acc[r]) + partD[0][jj * 5 + r] + partD[1][jj * 5 + r]
                            + partD[2][jj * 5 + r] + db2_j;
                    out[OFF_REC + ((size_t)t * BATCH + r0 + r) * OBS + jj] = v;
                }
            }
        }
        __syncthreads();   // S10
    }
}

// ---------------- host launch -------------------------------------------------
extern "C" void kernel_launch(void* const* d_in, const int* in_sizes, int n_in,
                              void* d_out, int out_size) {
    const float* x   = (const float*)d_in[0];
    const float* eps = (const float*)d_in[1];
    const float* Wih = (const float*)d_in[2];
    const float* Whh = (const float*)d_in[3];
    const float* bih = (const float*)d_in[4];
    const float* bhh = (const float*)d_in[5];
    const float* tW1 = (const float*)d_in[6];
    const float* tb1 = (const float*)d_in[7];
    const float* tW2 = (const float*)d_in[8];
    const float* tb2 = (const float*)d_in[9];
    const float* pW1 = (const float*)d_in[10];
    const float* pb1 = (const float*)d_in[11];
    const float* pW2 = (const float*)d_in[12];
    const float* pb2 = (const float*)d_in[13];
    const float* dW1 = (const float*)d_in[14];
    const float* db1 = (const float*)d_in[15];
    const float* dW2 = (const float*)d_in[16];
    const float* db2 = (const float*)d_in[17];
    float* out = (float*)d_out;

    static int smem_set = 0;
    if (!smem_set) {
        cudaFuncSetAttribute(gru_cluster_kernel,
                             cudaFuncAttributeMaxDynamicSharedMemorySize, GRU_SMEM_BYTES);
        smem_set = 1;
    }

    pack_all<<<64, 256>>>(tW1, tW2, pW1, pW2, dW1, dW2);

    dim3 g1(G3 / 64, (T_STEPS * BATCH) / 64);
    gx_kernel<<<g1, 256>>>(x, Wih, bih);

    gru_cluster_kernel<<<128, 384, GRU_SMEM_BYTES>>>(Whh, bhh);

    vrnn_kernel<<<64, 512>>>(eps, tb1, tb2, pb1, pb2, db1, db2, out);
}

// round 14
// speedup vs baseline: 2.2414x; 1.0860x over previous
#include <cuda_runtime.h>
#include <math.h>

#define T_STEPS 512
#define BATCH   256
#define OBS     128
#define LAT     64
#define HID     256
#define G3      (3*HID)      // 768
#define PIN     (HID+LAT)    // 320

// ---------------- scratch (device globals: allocation-free kernel_launch) ----
__device__ __align__(16) float g_gx[(size_t)T_STEPS*BATCH*G3];   // 384 MB
__device__ __align__(16) float g_hs[(size_t)T_STEPS*BATCH*HID];  // 128 MB
__device__ __align__(16) float g_tw1_p[HID*LAT];
__device__ __align__(16) float g_tw2_p[2*LAT*HID];
__device__ __align__(16) float g_pw1_p[HID*PIN];
__device__ __align__(16) float g_pw2_p[2*LAT*HID];
__device__ __align__(16) float g_dw1_p[HID*LAT];
__device__ __align__(16) float g_dw2_p[OBS*HID];

// output offsets (floats): recons | prior_mean | prior_logvar | post_mean | post_logvar
#define OFF_REC    0
#define OFF_PM     ((size_t)T_STEPS*BATCH*OBS)
#define OFF_PLV    (OFF_PM  + (size_t)T_STEPS*BATCH*LAT)
#define OFF_POSTM  (OFF_PLV + (size_t)T_STEPS*BATCH*LAT)
#define OFF_POSTLV (OFF_POSTM + (size_t)T_STEPS*BATCH*LAT)

// ---------------- helpers ----------------------------------------------------
__device__ __forceinline__ unsigned long long ffma2(unsigned long long a,
                                                    unsigned long long b,
                                                    unsigned long long c) {
    unsigned long long d;
    asm("fma.rn.f32x2 %0, %1, %2, %3;" : "=l"(d) : "l"(a), "l"(b), "l"(c));
    return d;
}
__device__ __forceinline__ float hsum2(unsigned long long v) {
    float lo, hi;
    asm("mov.b64 {%0, %1}, %2;" : "=f"(lo), "=f"(hi) : "l"(v));
    return lo + hi;
}
// fast activations: rel err ~1e-6, far inside the 1e-3 budget
__device__ __forceinline__ float fast_sigmoid(float x) {
    return __fdividef(1.f, 1.f + __expf(-x));
}
__device__ __forceinline__ float fast_tanh(float x) {
    return 1.f - __fdividef(2.f, __expf(2.f * x) + 1.f);
}

__device__ __forceinline__ unsigned smem_u32(const void* p) {
    unsigned a;
    asm("{ .reg .u64 t; cvta.to.shared.u64 t, %1; cvt.u32.u64 %0, t; }" : "=r"(a) : "l"(p));
    return a;
}
__device__ __forceinline__ void st_cluster_f32(unsigned addr, unsigned rank, float v) {
    asm volatile("{ .reg .b32 ra; mapa.shared::cluster.u32 ra, %0, %1; "
                 "st.shared::cluster.f32 [ra], %2; }"
                 :: "r"(addr), "r"(rank), "f"(v) : "memory");
}
__device__ __forceinline__ void cluster_sync_() {
    asm volatile("barrier.cluster.arrive.aligned;" ::: "memory");
    asm volatile("barrier.cluster.wait.aligned;" ::: "memory");
}

// ---------------- weight repack (vrnn only): [j][k] -> [(k/4)][j][k%4] -------
__device__ __forceinline__ void pack_seg(const float* __restrict__ s,
                                         float* __restrict__ d,
                                         int nout, int kin, int tid, int stride) {
    int total = nout * kin;
    for (int idx = tid; idx < total; idx += stride) {
        int j = idx / kin;
        int k = idx - j * kin;
        d[((k >> 2) * nout + j) * 4 + (k & 3)] = s[idx];
    }
}

__global__ void pack_all(const float* __restrict__ tW1, const float* __restrict__ tW2,
                         const float* __restrict__ pW1, const float* __restrict__ pW2,
                         const float* __restrict__ dW1, const float* __restrict__ dW2) {
    int tid = blockIdx.x * blockDim.x + threadIdx.x;
    int stride = gridDim.x * blockDim.x;
    pack_seg(tW1, g_tw1_p, HID,   LAT, tid, stride);
    pack_seg(tW2, g_tw2_p, 2*LAT, HID, tid, stride);
    pack_seg(pW1, g_pw1_p, HID,   PIN, tid, stride);
    pack_seg(pW2, g_pw2_p, 2*LAT, HID, tid, stride);
    pack_seg(dW1, g_dw1_p, HID,   LAT, tid, stride);
    pack_seg(dW2, g_dw2_p, OBS,   HID, tid, stride);
}

// ---------------- K1: gx = x @ W_ih^T + b_ih ---------------------------------
__global__ void __launch_bounds__(256) gx_kernel(const float* __restrict__ x,
                                                 const float* __restrict__ Wih,
                                                 const float* __restrict__ bih) {
    __shared__ float xs[64][68];
    __shared__ float wsm[64][68];
    const int tid = threadIdx.x;
    const int ty = tid >> 4, tx = tid & 15;
    const int m0 = blockIdx.y * 64;
    const int n0 = blockIdx.x * 64;

    unsigned long long acc[4][4];
    #pragma unroll
    for (int i = 0; i < 4; i++)
        #pragma unroll
        for (int j = 0; j < 4; j++) acc[i][j] = 0ull;

    #pragma unroll
    for (int k0 = 0; k0 < OBS; k0 += 64) {
        #pragma unroll
        for (int p = 0; p < 4; p++) {
            int idx4 = tid + 256 * p;
            int row = idx4 >> 4;
            int c   = (idx4 & 15) * 4;
            *(float4*)&xs [row][c] = *(const float4*)&x  [(size_t)(m0 + row) * OBS + k0 + c];
            *(float4*)&wsm[row][c] = *(const float4*)&Wih[(size_t)(n0 + row) * OBS + k0 + c];
        }
        __syncthreads();
        #pragma unroll
        for (int k2 = 0; k2 < 32; k2++) {
            unsigned long long a[4], b[4];
            #pragma unroll
            for (int i = 0; i < 4; i++) a[i] = *(const unsigned long long*)&xs [ty + 16 * i][2 * k2];
            #pragma unroll
            for (int j = 0; j < 4; j++) b[j] = *(const unsigned long long*)&wsm[tx + 16 * j][2 * k2];
            #pragma unroll
            for (int i = 0; i < 4; i++)
                #pragma unroll
                for (int j = 0; j < 4; j++) acc[i][j] = ffma2(a[i], b[j], acc[i][j]);
        }
        __syncthreads();
    }
    #pragma unroll
    for (int i = 0; i < 4; i++) {
        int m = m0 + ty + 16 * i;
        #pragma unroll
        for (int j = 0; j < 4; j++) {
            int n = n0 + tx + 16 * j;
            g_gx[(size_t)m * G3 + n] = hsum2(acc[i][j]) + bih[n];
        }
    }
}

// ---------------- K2: GRU scan, 4-CTA clusters, 768 threads ------------------
// Cluster = 8 batch rows. CTA rank c owns hidden [64c,64c+64) (192 gate rows).
// 24 warps: 4-way k-split of the GEMV; reduction via [r][192] smem buffers.
#define GRU_THREADS   768
#define GRU_WS_FLOATS (64*192*4)              // 49152 floats: ws[k4][192][4]
#define GRU_H_FLOATS  (2*8*256)               // 4096
#define GRU_GH_FLOATS (8*192)                 // 1536, layout [r][l]
#define GRU_SMEM_BYTES ((GRU_WS_FLOATS + GRU_H_FLOATS + 3*GRU_GH_FLOATS)*4) // 231424

__global__ void __launch_bounds__(GRU_THREADS, 1) __cluster_dims__(4, 1, 1)
gru_cluster_kernel(const float* __restrict__ Whh, const float* __restrict__ bhh) {
    extern __shared__ float sm[];
    float* ws    = sm;                        // [k4][192][4]
    float* hbuf  = ws + GRU_WS_FLOATS;        // [2][8][256]
    float* gh    = hbuf + GRU_H_FLOATS;       // [8][192]
    float* partA = gh + GRU_GH_FLOATS;        // [8][192]
    float* partB = partA + GRU_GH_FLOATS;     // [8][192]

    unsigned rank; asm("mov.u32 %0, %%cluster_ctarank;" : "=r"(rank));
    const int tid = threadIdx.x;
    const int r0  = (blockIdx.x >> 2) * 8;    // first batch row of cluster

    // one-time load of this CTA's 192 gate rows of W_hh, layout [k4][l][4]
    for (int idx = tid; idx < 192 * 64; idx += GRU_THREADS) {
        int k4 = idx / 192, l = idx - k4 * 192;
        int g = l >> 6, il = l & 63;
        int j = g * 256 + (int)rank * 64 + il;
        *(float4*)&ws[(size_t)idx * 4] = *(const float4*)&Whh[(size_t)j * 256 + k4 * 4];
    }
    for (int idx = tid; idx < GRU_H_FLOATS; idx += GRU_THREADS) hbuf[idx] = 0.f;

    const int l  = tid % 192;                 // gate row
    const int kq = tid / 192;                 // k-quarter 0..3
    const int gg = l >> 6, il = l & 63;
    const float bias = bhh[gg * 256 + (int)rank * 64 + il];
    const unsigned hbuf_u32 = smem_u32(hbuf);

    // partial-store destination for this thread's k-quarter (kq 1/2/3 write,
    // kq 0 accumulates). kq==0 threads get gh but never use dst as a store.
    float* dst = (kq == 3) ? gh : ((kq == 2) ? partA : partB);

    __syncthreads();
    cluster_sync_();                          // peers' h init before step-0 remote writes

    int buf = 0;
    for (int t = 0; t < T_STEPS; t++) {
        // prefetch gx (consumed in the pointwise, thousands of cycles later)
        float gx0 = 0.f, gx1 = 0.f, gx2 = 0.f;
        if (tid < 512) {
            int r = tid >> 6, il2 = tid & 63;
            size_t base = ((size_t)t * BATCH + r0 + r) * G3 + rank * 64 + il2;
            gx0 = g_gx[base]; gx1 = g_gx[base + 256]; gx2 = g_gx[base + 512];
        }
        // GEMV: this thread covers gate row l, k-quarter kq, all 8 rows
        unsigned long long acc[8] = {0,0,0,0,0,0,0,0};
        const float* hb = hbuf + buf * 2048;
        #pragma unroll 4
        for (int kk = 0; kk < 16; kk++) {
            int k4 = kq * 16 + kk;
            ulonglong2 w = *(const ulonglong2*)&ws[(k4 * 192 + l) * 4];
            #pragma unroll
            for (int r = 0; r < 8; r++) {
                ulonglong2 hv = *(const ulonglong2*)&hb[r * 256 + k4 * 4];
                acc[r] = ffma2(hv.x, w.x, acc[r]);
                acc[r] = ffma2(hv.y, w.y, acc[r]);
            }
        }
        float v[8];
        #pragma unroll
        for (int r = 0; r < 8; r++) v[r] = hsum2(acc[r]);
        if (kq != 0) {
            #pragma unroll
            for (int r = 0; r < 8; r++) dst[r * 192 + l] = v[r];
        }
        __syncthreads();
        if (kq == 0) {
            #pragma unroll
            for (int r = 0; r < 8; r++)
                gh[r * 192 + l] = v[r] + gh[r * 192 + l] + partA[r * 192 + l]
                                + partB[r * 192 + l] + bias;
        }
        __syncthreads();
        // pointwise + h exchange (512 items: 8 rows x 64 local hidden)
        if (tid < 512) {
            int r = tid >> 6, il2 = tid & 63;
            float hr_ = gh[r * 192 + il2];
            float hz_ = gh[r * 192 + 64 + il2];
            float hn_ = gh[r * 192 + 128 + il2];
            float rg = fast_sigmoid(gx0 + hr_);
            float zg = fast_sigmoid(gx1 + hz_);
            float ng = fast_tanh(gx2 + rg * hn_);
            float hold = hb[r * 256 + rank * 64 + il2];
            float hnew = (1.f - zg) * ng + zg * hold;
            unsigned off = (unsigned)(((buf ^ 1) * 2048 + r * 256 + (int)rank * 64 + il2) * 4);
            #pragma unroll
            for (int pr = 0; pr < 4; pr++) st_cluster_f32(hbuf_u32 + off, (unsigned)pr, hnew);
            g_hs[((size_t)t * BATCH + r0 + r) * HID + rank * 64 + il2] = hnew;
        }
        cluster_sync_();
        buf ^= 1;
    }
}

// ---------------- K3: vrnn scan, 512 threads, split-K, 8-deep MLP ------------
__global__ void __launch_bounds__(512, 1) vrnn_kernel(
        const float* __restrict__ eps,
        const float* __restrict__ tb1, const float* __restrict__ tb2,
        const float* __restrict__ pb1, const float* __restrict__ pb2,
        const float* __restrict__ db1, const float* __restrict__ db2,
        float* __restrict__ out) {
    __shared__ float pin_s[4][PIN];
    __shared__ float a1_s[4][HID];
    __shared__ float a2_s[4][HID];
    __shared__ float post_s[4][2 * LAT];
    __shared__ float partA[256 * 5];
    __shared__ float partB[256 * 5];
    __shared__ float partD[3][128 * 5];

    const int tid = threadIdx.x;
    const int r0  = blockIdx.x * 4;
    const int j2  = tid & 255;
    const int s2  = tid >> 8;
    const int jj  = tid & 127;
    const int head = (tid >> 7) & 1;
    const int sD  = tid >> 7;

    { int r = tid >> 7, lz = tid & 127; if (lz < 64) pin_s[r][HID + lz] = 0.f; }

    const float tb1_j = tb1[j2];
    const float pb1_j = pb1[j2];
    const float db1_j = db1[j2];
    const float bB    = head ? pb2[jj] : tb2[jj];
    const float db2_j = db2[jj];

    const ulonglong2* __restrict__ tw1p = (const ulonglong2*)g_tw1_p;
    const ulonglong2* __restrict__ pw1p = (const ulonglong2*)g_pw1_p;
    const ulonglong2* __restrict__ dw1p = (const ulonglong2*)g_dw1_p;
    const ulonglong2* __restrict__ dw2p = (const ulonglong2*)g_dw2_p;
    const ulonglong2* __restrict__ w2p  = head ? (const ulonglong2*)g_pw2_p
                                               : (const ulonglong2*)g_tw2_p;
    const float* asrc = head ? &a2_s[0][0] : &a1_s[0][0];
    __syncthreads();

    ulonglong2 wreg[8];

    for (int t = 0; t < T_STEPS; t++) {
        float epv = 0.f;
        if (tid < 256)
            epv = eps[((size_t)t * BATCH + r0 + (tid >> 6)) * LAT + (tid & 63)];

        {
            size_t base = ((size_t)t * BATCH + r0) * HID;
            #pragma unroll
            for (int q = 0; q < 2; q++) {
                int idx = tid + q * 512;
                int r = idx >> 8, c = idx & 255;
                pin_s[r][c] = g_hs[base + (size_t)r * HID + c];
            }
        }
        __syncthreads();   // S1

        // ---- Stage A: prior hidden (K=64, split2) — one 8-deep block
        float ownA[4], ownA2[4];
        {
            #pragma unroll
            for (int u = 0; u < 8; u++) wreg[u] = tw1p[(s2 * 8 + u) * HID + j2];
            unsigned long long acc[4] = {0,0,0,0};
            #pragma unroll
            for (int u = 0; u < 8; u++) {
                int k4 = s2 * 8 + u;
                #pragma unroll
                for (int r = 0; r < 4; r++) {
                    ulonglong2 av = *(const ulonglong2*)&pin_s[r][HID + k4 * 4];
                    acc[r] = ffma2(av.x, wreg[u].x, acc[r]);
                    acc[r] = ffma2(av.y, wreg[u].y, acc[r]);
                }
            }
            #pragma unroll
            for (int r = 0; r < 4; r++) ownA[r] = hsum2(acc[r]);
        }
        // ---- Stage A2: posterior hidden (K=320, split2) — five 8-deep blocks
        {
            unsigned long long acc[4] = {0,0,0,0};
            for (int blk = 0; blk < 5; blk++) {
                int kb = s2 * 40 + blk * 8;
                #pragma unroll
                for (int u = 0; u < 8; u++) wreg[u] = pw1p[(kb + u) * HID + j2];
                #pragma unroll
                for (int u = 0; u < 8; u++) {
                    int k4 = kb + u;
                    #pragma unroll
                    for (int r = 0; r < 4; r++) {
                        ulonglong2 av = *(const ulonglong2*)&pin_s[r][k4 * 4];
                        acc[r] = ffma2(av.x, wreg[u].x, acc[r]);
                        acc[r] = ffma2(av.y, wreg[u].y, acc[r]);
                    }
                }
            }
            #pragma unroll
            for (int r = 0; r < 4; r++) ownA2[r] = hsum2(acc[r]);
        }
        if (s2) {
            #pragma unroll
            for (int r = 0; r < 4; r++) { partA[j2 * 5 + r] = ownA[r]; partB[j2 * 5 + r] = ownA2[r]; }
        }
        __syncthreads();   // S2
        if (!s2) {
            #pragma unroll
            for (int r = 0; r < 4; r++) {
                a1_s[r][j2] = fmaxf(ownA[r]  + partA[j2 * 5 + r] + tb1_j, 0.f);
                a2_s[r][j2] = fmaxf(ownA2[r] + partB[j2 * 5 + r] + pb1_j, 0.f);
            }
        }
        __syncthreads();   // S3

        // ---- Stage B: heads (K=256, split2) — four 8-deep blocks
        {
            unsigned long long acc[4] = {0,0,0,0};
            for (int blk = 0; blk < 4; blk++) {
                int kb = s2 * 32 + blk * 8;
                #pragma unroll
                for (int u = 0; u < 8; u++) wreg[u] = w2p[(kb + u) * 128 + jj];
                #pragma unroll
                for (int u = 0; u < 8; u++) {
                    int k4 = kb + u;
                    #pragma unroll
                    for (int r = 0; r < 4; r++) {
                        ulonglong2 av = *(const ulonglong2*)(asrc + r * HID + k4 * 4);
                        acc[r] = ffma2(av.x, wreg[u].x, acc[r]);
                        acc[r] = ffma2(av.y, wreg[u].y, acc[r]);
                    }
                }
            }
            if (s2) {
                #pragma unroll
                for (int r = 0; r < 4; r++) partA[(head * 128 + jj) * 5 + r] = hsum2(acc[r]);
            }
            __syncthreads();   // S4
            if (!s2) {
                int tb = t * BATCH + r0;
                #pragma unroll
                for (int r = 0; r < 4; r++) {
                    float v = hsum2(acc[r]) + partA[(head * 128 + jj) * 5 + r] + bB;
                    size_t orow = (size_t)(tb + r) * LAT;
                    if (head) {
                        post_s[r][jj] = v;
                        if (jj < 64) out[OFF_POSTM  + orow + jj]      = v;
                        else         out[OFF_POSTLV + orow + jj - 64] = v;
                    } else {
                        if (jj < 64) out[OFF_PM  + orow + jj]      = v;
                        else         out[OFF_PLV + orow + jj - 64] = v;
                    }
                }
            }
        }
        __syncthreads();   // S5

        // ---- z update
        if (tid < 256) {
            int r = tid >> 6, lz = tid & 63;
            float pm  = post_s[r][lz];
            float plv = post_s[r][LAT + lz];
            pin_s[r][HID + lz] = pm + epv * __expf(0.5f * plv);
        }
        __syncthreads();   // S6

        // ---- Stage C: decoder hidden (K=64, split2) — one 8-deep block
        {
            #pragma unroll
            for (int u = 0; u < 8; u++) wreg[u] = dw1p[(s2 * 8 + u) * HID + j2];
            unsigned long long acc[4] = {0,0,0,0};
            #pragma unroll
            for (int u = 0; u < 8; u++) {
                int k4 = s2 * 8 + u;
                #pragma unroll
                for (int r = 0; r < 4; r++) {
                    ulonglong2 av = *(const ulonglong2*)&pin_s[r][HID + k4 * 4];
                    acc[r] = ffma2(av.x, wreg[u].x, acc[r]);
                    acc[r] = ffma2(av.y, wreg[u].y, acc[r]);
                }
            }
            if (s2) {
                #pragma unroll
                for (int r = 0; r < 4; r++) partB[j2 * 5 + r] = hsum2(acc[r]);
            }
            __syncthreads();   // S7
            if (!s2) {
                #pragma unroll
                for (int r = 0; r < 4; r++)
                    a1_s[r][j2] = fmaxf(hsum2(acc[r]) + partB[j2 * 5 + r] + db1_j, 0.f);
            }
        }
        __syncthreads();   // S8

        // ---- Stage D: recon (K=256, split4) — two 8-deep blocks
        {
            unsigned long long acc[4] = {0,0,0,0};
            for (int blk = 0; blk < 2; blk++) {
                int kb = sD * 16 + blk * 8;
                #pragma unroll
                for (int u = 0; u < 8; u++) wreg[u] = dw2p[(kb + u) * 128 + jj];
                #pragma unroll
                for (int u = 0; u < 8; u++) {
                    int k4 = kb + u;
                    #pragma unroll
                    for (int r = 0; r < 4; r++) {
                        ulonglong2 av = *(const ulonglong2*)&a1_s[r][k4 * 4];
                        acc[r] = ffma2(av.x, wreg[u].x, acc[r]);
                        acc[r] = ffma2(av.y, wreg[u].y, acc[r]);
                    }
                }
            }
            if (sD) {
                #pragma unroll
                for (int r = 0; r < 4; r++) partD[sD - 1][jj * 5 + r] = hsum2(acc[r]);
            }
            __syncthreads();   // S9
            if (sD == 0) {
                #pragma unroll
                for (int r = 0; r < 4; r++) {
                    float v = hsum2(acc[r]) + partD[0][jj * 5 + r] + partD[1][jj * 5 + r]
                            + partD[2][jj * 5 + r] + db2_j;
                    out[OFF_REC + ((size_t)t * BATCH + r0 + r) * OBS + jj] = v;
                }
            }
        }
        __syncthreads();   // S10
    }
}

// ---------------- host launch -------------------------------------------------
extern "C" void kernel_launch(void* const* d_in, const int* in_sizes, int n_in,
                              void* d_out, int out_size) {
    const float* x   = (const float*)d_in[0];
    const float* eps = (const float*)d_in[1];
    const float* Wih = (const float*)d_in[2];
    const float* Whh = (const float*)d_in[3];
    const float* bih = (const float*)d_in[4];
    const float* bhh = (const float*)d_in[5];
    const float* tW1 = (const float*)d_in[6];
    const float* tb1 = (const float*)d_in[7];
    const float* tW2 = (const float*)d_in[8];
    const float* tb2 = (const float*)d_in[9];
    const float* pW1 = (const float*)d_in[10];
    const float* pb1 = (const float*)d_in[11];
    const float* pW2 = (const float*)d_in[12];
    const float* pb2 = (const float*)d_in[13];
    const float* dW1 = (const float*)d_in[14];
    const float* db1 = (const float*)d_in[15];
    const float* dW2 = (const float*)d_in[16];
    const float* db2 = (const float*)d_in[17];
    float* out = (float*)d_out;

    static int smem_set = 0;
    if (!smem_set) {
        cudaFuncSetAttribute(gru_cluster_kernel,
                             cudaFuncAttributeMaxDynamicSharedMemorySize, GRU_SMEM_BYTES);
        smem_set = 1;
    }

    pack_all<<<64, 256>>>(tW1, tW2, pW1, pW2, dW1, dW2);

    dim3 g1(G3 / 64, (T_STEPS * BATCH) / 64);
    gx_kernel<<<g1, 256>>>(x, Wih, bih);

    gru_cluster_kernel<<<128, GRU_THREADS, GRU_SMEM_BYTES>>>(Whh, bhh);

    vrnn_kernel<<<64, 512>>>(eps, tb1, tb2, pb1, pb2, db1, db2, out);
}

// round 15
// speedup vs baseline: 2.2419x; 1.0002x over previous
#include <cuda_runtime.h>
#include <math.h>

#define T_STEPS 512
#define BATCH   256
#define OBS     128
#define LAT     64
#define HID     256
#define G3      (3*HID)      // 768
#define PIN     (HID+LAT)    // 320

// ---------------- scratch (device globals: allocation-free kernel_launch) ----
__device__ __align__(16) float g_gx[(size_t)T_STEPS*BATCH*G3];   // 384 MB
__device__ __align__(16) float g_hs[(size_t)T_STEPS*BATCH*HID];  // 128 MB
__device__ __align__(16) float g_tw1_p[HID*LAT];
__device__ __align__(16) float g_tw2_p[2*LAT*HID];
__device__ __align__(16) float g_pw1_p[HID*PIN];
__device__ __align__(16) float g_pw2_p[2*LAT*HID];
__device__ __align__(16) float g_dw1_p[HID*LAT];
__device__ __align__(16) float g_dw2_p[OBS*HID];

// output offsets (floats): recons | prior_mean | prior_logvar | post_mean | post_logvar
#define OFF_REC    0
#define OFF_PM     ((size_t)T_STEPS*BATCH*OBS)
#define OFF_PLV    (OFF_PM  + (size_t)T_STEPS*BATCH*LAT)
#define OFF_POSTM  (OFF_PLV + (size_t)T_STEPS*BATCH*LAT)
#define OFF_POSTLV (OFF_POSTM + (size_t)T_STEPS*BATCH*LAT)

// ---------------- helpers ----------------------------------------------------
__device__ __forceinline__ unsigned long long ffma2(unsigned long long a,
                                                    unsigned long long b,
                                                    unsigned long long c) {
    unsigned long long d;
    asm("fma.rn.f32x2 %0, %1, %2, %3;" : "=l"(d) : "l"(a), "l"(b), "l"(c));
    return d;
}
__device__ __forceinline__ float hsum2(unsigned long long v) {
    float lo, hi;
    asm("mov.b64 {%0, %1}, %2;" : "=f"(lo), "=f"(hi) : "l"(v));
    return lo + hi;
}
// fast activations: rel err ~1e-6, far inside the 1e-3 budget
__device__ __forceinline__ float fast_sigmoid(float x) {
    return __fdividef(1.f, 1.f + __expf(-x));
}
__device__ __forceinline__ float fast_tanh(float x) {
    return 1.f - __fdividef(2.f, __expf(2.f * x) + 1.f);
}

__device__ __forceinline__ unsigned smem_u32(const void* p) {
    unsigned a;
    asm("{ .reg .u64 t; cvta.to.shared.u64 t, %1; cvt.u32.u64 %0, t; }" : "=r"(a) : "l"(p));
    return a;
}
__device__ __forceinline__ void st_cluster_f32(unsigned addr, unsigned rank, float v) {
    asm volatile("{ .reg .b32 ra; mapa.shared::cluster.u32 ra, %0, %1; "
                 "st.shared::cluster.f32 [ra], %2; }"
                 :: "r"(addr), "r"(rank), "f"(v) : "memory");
}
__device__ __forceinline__ void cluster_sync_() {
    asm volatile("barrier.cluster.arrive.aligned;" ::: "memory");
    asm volatile("barrier.cluster.wait.aligned;" ::: "memory");
}

// ---------------- weight repack (vrnn only): [j][k] -> [(k/4)][j][k%4] -------
__device__ __forceinline__ void pack_seg(const float* __restrict__ s,
                                         float* __restrict__ d,
                                         int nout, int kin, int tid, int stride) {
    int total = nout * kin;
    for (int idx = tid; idx < total; idx += stride) {
        int j = idx / kin;
        int k = idx - j * kin;
        d[((k >> 2) * nout + j) * 4 + (k & 3)] = s[idx];
    }
}

__global__ void pack_all(const float* __restrict__ tW1, const float* __restrict__ tW2,
                         const float* __restrict__ pW1, const float* __restrict__ pW2,
                         const float* __restrict__ dW1, const float* __restrict__ dW2) {
    int tid = blockIdx.x * blockDim.x + threadIdx.x;
    int stride = gridDim.x * blockDim.x;
    pack_seg(tW1, g_tw1_p, HID,   LAT, tid, stride);
    pack_seg(tW2, g_tw2_p, 2*LAT, HID, tid, stride);
    pack_seg(pW1, g_pw1_p, HID,   PIN, tid, stride);
    pack_seg(pW2, g_pw2_p, 2*LAT, HID, tid, stride);
    pack_seg(dW1, g_dw1_p, HID,   LAT, tid, stride);
    pack_seg(dW2, g_dw2_p, OBS,   HID, tid, stride);
}

// ---------------- K1: gx = x @ W_ih^T + b_ih ---------------------------------
__global__ void __launch_bounds__(256) gx_kernel(const float* __restrict__ x,
                                                 const float* __restrict__ Wih,
                                                 const float* __restrict__ bih) {
    __shared__ float xs[64][68];
    __shared__ float wsm[64][68];
    const int tid = threadIdx.x;
    const int ty = tid >> 4, tx = tid & 15;
    const int m0 = blockIdx.y * 64;
    const int n0 = blockIdx.x * 64;

    unsigned long long acc[4][4];
    #pragma unroll
    for (int i = 0; i < 4; i++)
        #pragma unroll
        for (int j = 0; j < 4; j++) acc[i][j] = 0ull;

    #pragma unroll
    for (int k0 = 0; k0 < OBS; k0 += 64) {
        #pragma unroll
        for (int p = 0; p < 4; p++) {
            int idx4 = tid + 256 * p;
            int row = idx4 >> 4;
            int c   = (idx4 & 15) * 4;
            *(float4*)&xs [row][c] = *(const float4*)&x  [(size_t)(m0 + row) * OBS + k0 + c];
            *(float4*)&wsm[row][c] = *(const float4*)&Wih[(size_t)(n0 + row) * OBS + k0 + c];
        }
        __syncthreads();
        #pragma unroll
        for (int k2 = 0; k2 < 32; k2++) {
            unsigned long long a[4], b[4];
            #pragma unroll
            for (int i = 0; i < 4; i++) a[i] = *(const unsigned long long*)&xs [ty + 16 * i][2 * k2];
            #pragma unroll
            for (int j = 0; j < 4; j++) b[j] = *(const unsigned long long*)&wsm[tx + 16 * j][2 * k2];
            #pragma unroll
            for (int i = 0; i < 4; i++)
                #pragma unroll
                for (int j = 0; j < 4; j++) acc[i][j] = ffma2(a[i], b[j], acc[i][j]);
        }
        __syncthreads();
    }
    #pragma unroll
    for (int i = 0; i < 4; i++) {
        int m = m0 + ty + 16 * i;
        #pragma unroll
        for (int j = 0; j < 4; j++) {
            int n = n0 + tx + 16 * j;
            g_gx[(size_t)m * G3 + n] = hsum2(acc[i][j]) + bih[n];
        }
    }
}

// ---------------- K2: GRU scan, 4-CTA clusters, 768 threads ------------------
// Cluster = 8 batch rows. CTA rank c owns hidden [64c,64c+64) (192 gate rows).
// 24 warps: 4-way k-split of the GEMV; reduction via [r][192] smem buffers.
#define GRU_THREADS   768
#define GRU_WS_FLOATS (64*192*4)              // 49152 floats: ws[k4][192][4]
#define GRU_H_FLOATS  (2*8*256)               // 4096
#define GRU_GH_FLOATS (8*192)                 // 1536, layout [r][l]
#define GRU_SMEM_BYTES ((GRU_WS_FLOATS + GRU_H_FLOATS + 3*GRU_GH_FLOATS)*4) // 231424

__global__ void __launch_bounds__(GRU_THREADS, 1) __cluster_dims__(4, 1, 1)
gru_cluster_kernel(const float* __restrict__ Whh, const float* __restrict__ bhh) {
    extern __shared__ float sm[];
    float* ws    = sm;                        // [k4][192][4]
    float* hbuf  = ws + GRU_WS_FLOATS;        // [2][8][256]
    float* gh    = hbuf + GRU_H_FLOATS;       // [8][192]
    float* partA = gh + GRU_GH_FLOATS;        // [8][192]
    float* partB = partA + GRU_GH_FLOATS;     // [8][192]

    unsigned rank; asm("mov.u32 %0, %%cluster_ctarank;" : "=r"(rank));
    const int tid = threadIdx.x;
    const int r0  = (blockIdx.x >> 2) * 8;    // first batch row of cluster

    // one-time load of this CTA's 192 gate rows of W_hh, layout [k4][l][4]
    for (int idx = tid; idx < 192 * 64; idx += GRU_THREADS) {
        int k4 = idx / 192, l = idx - k4 * 192;
        int g = l >> 6, il = l & 63;
        int j = g * 256 + (int)rank * 64 + il;
        *(float4*)&ws[(size_t)idx * 4] = *(const float4*)&Whh[(size_t)j * 256 + k4 * 4];
    }
    for (int idx = tid; idx < GRU_H_FLOATS; idx += GRU_THREADS) hbuf[idx] = 0.f;

    const int l  = tid % 192;                 // gate row
    const int kq = tid / 192;                 // k-quarter 0..3
    const int gg = l >> 6, il = l & 63;
    const float bias = bhh[gg * 256 + (int)rank * 64 + il];
    const unsigned hbuf_u32 = smem_u32(hbuf);

    // partial-store destination for this thread's k-quarter (kq 1/2/3 write,
    // kq 0 accumulates). kq==0 threads get gh but never use dst as a store.
    float* dst = (kq == 3) ? gh : ((kq == 2) ? partA : partB);

    __syncthreads();
    cluster_sync_();                          // peers' h init before step-0 remote writes

    int buf = 0;
    for (int t = 0; t < T_STEPS; t++) {
        // prefetch gx (consumed in the pointwise, thousands of cycles later)
        float gx0 = 0.f, gx1 = 0.f, gx2 = 0.f;
        if (tid < 512) {
            int r = tid >> 6, il2 = tid & 63;
            size_t base = ((size_t)t * BATCH + r0 + r) * G3 + rank * 64 + il2;
            gx0 = g_gx[base]; gx1 = g_gx[base + 256]; gx2 = g_gx[base + 512];
        }
        // GEMV: this thread covers gate row l, k-quarter kq, all 8 rows
        unsigned long long acc[8] = {0,0,0,0,0,0,0,0};
        const float* hb = hbuf + buf * 2048;
        #pragma unroll 4
        for (int kk = 0; kk < 16; kk++) {
            int k4 = kq * 16 + kk;
            ulonglong2 w = *(const ulonglong2*)&ws[(k4 * 192 + l) * 4];
            #pragma unroll
            for (int r = 0; r < 8; r++) {
                ulonglong2 hv = *(const ulonglong2*)&hb[r * 256 + k4 * 4];
                acc[r] = ffma2(hv.x, w.x, acc[r]);
                acc[r] = ffma2(hv.y, w.y, acc[r]);
            }
        }
        float v[8];
        #pragma unroll
        for (int r = 0; r < 8; r++) v[r] = hsum2(acc[r]);
        if (kq != 0) {
            #pragma unroll
            for (int r = 0; r < 8; r++) dst[r * 192 + l] = v[r];
        }
        __syncthreads();
        if (kq == 0) {
            #pragma unroll
            for (int r = 0; r < 8; r++)
                gh[r * 192 + l] = v[r] + gh[r * 192 + l] + partA[r * 192 + l]
                                + partB[r * 192 + l] + bias;
        }
        __syncthreads();
        // pointwise + h exchange (512 items: 8 rows x 64 local hidden)
        if (tid < 512) {
            int r = tid >> 6, il2 = tid & 63;
            float hr_ = gh[r * 192 + il2];
            float hz_ = gh[r * 192 + 64 + il2];
            float hn_ = gh[r * 192 + 128 + il2];
            float rg = fast_sigmoid(gx0 + hr_);
            float zg = fast_sigmoid(gx1 + hz_);
            float ng = fast_tanh(gx2 + rg * hn_);
            float hold = hb[r * 256 + rank * 64 + il2];
            float hnew = (1.f - zg) * ng + zg * hold;
            unsigned off = (unsigned)(((buf ^ 1) * 2048 + r * 256 + (int)rank * 64 + il2) * 4);
            #pragma unroll
            for (int pr = 0; pr < 4; pr++) st_cluster_f32(hbuf_u32 + off, (unsigned)pr, hnew);
            g_hs[((size_t)t * BATCH + r0 + r) * HID + rank * 64 + il2] = hnew;
        }
        cluster_sync_();
        buf ^= 1;
    }
}

// ---------------- K3: vrnn scan, 512 threads, split-K, 8-deep MLP ------------
__global__ void __launch_bounds__(512, 1) vrnn_kernel(
        const float* __restrict__ eps,
        const float* __restrict__ tb1, const float* __restrict__ tb2,
        const float* __restrict__ pb1, const float* __restrict__ pb2,
        const float* __restrict__ db1, const float* __restrict__ db2,
        float* __restrict__ out) {
    __shared__ float pin_s[4][PIN];
    __shared__ float a1_s[4][HID];
    __shared__ float a2_s[4][HID];
    __shared__ float post_s[4][2 * LAT];
    __shared__ float partA[256 * 5];
    __shared__ float partB[256 * 5];
    __shared__ float partD[3][128 * 5];

    const int tid = threadIdx.x;
    const int r0  = blockIdx.x * 4;
    const int j2  = tid & 255;
    const int s2  = tid >> 8;
    const int jj  = tid & 127;
    const int head = (tid >> 7) & 1;
    const int sD  = tid >> 7;

    { int r = tid >> 7, lz = tid & 127; if (lz < 64) pin_s[r][HID + lz] = 0.f; }

    const float tb1_j = tb1[j2];
    const float pb1_j = pb1[j2];
    const float db1_j = db1[j2];
    const float bB    = head ? pb2[jj] : tb2[jj];
    const float db2_j = db2[jj];

    const ulonglong2* __restrict__ tw1p = (const ulonglong2*)g_tw1_p;
    const ulonglong2* __restrict__ pw1p = (const ulonglong2*)g_pw1_p;
    const ulonglong2* __restrict__ dw1p = (const ulonglong2*)g_dw1_p;
    const ulonglong2* __restrict__ dw2p = (const ulonglong2*)g_dw2_p;
    const ulonglong2* __restrict__ w2p  = head ? (const ulonglong2*)g_pw2_p
                                               : (const ulonglong2*)g_tw2_p;
    const float* asrc = head ? &a2_s[0][0] : &a1_s[0][0];
    __syncthreads();

    ulonglong2 wreg[8];

    for (int t = 0; t < T_STEPS; t++) {
        float epv = 0.f;
        if (tid < 256)
            epv = eps[((size_t)t * BATCH + r0 + (tid >> 6)) * LAT + (tid & 63)];

        {
            size_t base = ((size_t)t * BATCH + r0) * HID;
            #pragma unroll
            for (int q = 0; q < 2; q++) {
                int idx = tid + q * 512;
                int r = idx >> 8, c = idx & 255;
                pin_s[r][c] = g_hs[base + (size_t)r * HID + c];
            }
        }
        __syncthreads();   // S1

        // ---- Stage A: prior hidden (K=64, split2) — one 8-deep block
        float ownA[4], ownA2[4];
        {
            #pragma unroll
            for (int u = 0; u < 8; u++) wreg[u] = tw1p[(s2 * 8 + u) * HID + j2];
            unsigned long long acc[4] = {0,0,0,0};
            #pragma unroll
            for (int u = 0; u < 8; u++) {
                int k4 = s2 * 8 + u;
                #pragma unroll
                for (int r = 0; r < 4; r++) {
                    ulonglong2 av = *(const ulonglong2*)&pin_s[r][HID + k4 * 4];
                    acc[r] = ffma2(av.x, wreg[u].x, acc[r]);
                    acc[r] = ffma2(av.y, wreg[u].y, acc[r]);
                }
            }
            #pragma unroll
            for (int r = 0; r < 4; r++) ownA[r] = hsum2(acc[r]);
        }
        // ---- Stage A2: posterior hidden (K=320, split2) — five 8-deep blocks
        {
            unsigned long long acc[4] = {0,0,0,0};
            for (int blk = 0; blk < 5; blk++) {
                int kb = s2 * 40 + blk * 8;
                #pragma unroll
                for (int u = 0; u < 8; u++) wreg[u] = pw1p[(kb + u) * HID + j2];
                #pragma unroll
                for (int u = 0; u < 8; u++) {
                    int k4 = kb + u;
                    #pragma unroll
                    for (int r = 0; r < 4; r++) {
                        ulonglong2 av = *(const ulonglong2*)&pin_s[r][k4 * 4];
                        acc[r] = ffma2(av.x, wreg[u].x, acc[r]);
                        acc[r] = ffma2(av.y, wreg[u].y, acc[r]);
                    }
                }
            }
            #pragma unroll
            for (int r = 0; r < 4; r++) ownA2[r] = hsum2(acc[r]);
        }
        if (s2) {
            #pragma unroll
            for (int r = 0; r < 4; r++) { partA[j2 * 5 + r] = ownA[r]; partB[j2 * 5 + r] = ownA2[r]; }
        }
        __syncthreads();   // S2
        if (!s2) {
            #pragma unroll
            for (int r = 0; r < 4; r++) {
                a1_s[r][j2] = fmaxf(ownA[r]  + partA[j2 * 5 + r] + tb1_j, 0.f);
                a2_s[r][j2] = fmaxf(ownA2[r] + partB[j2 * 5 + r] + pb1_j, 0.f);
            }
        }
        __syncthreads();   // S3

        // ---- Stage B: heads (K=256, split2) — four 8-deep blocks
        {
            unsigned long long acc[4] = {0,0,0,0};
            for (int blk = 0; blk < 4; blk++) {
                int kb = s2 * 32 + blk * 8;
                #pragma unroll
                for (int u = 0; u < 8; u++) wreg[u] = w2p[(kb + u) * 128 + jj];
                #pragma unroll
                for (int u = 0; u < 8; u++) {
                    int k4 = kb + u;
                    #pragma unroll
                    for (int r = 0; r < 4; r++) {
                        ulonglong2 av = *(const ulonglong2*)(asrc + r * HID + k4 * 4);
                        acc[r] = ffma2(av.x, wreg[u].x, acc[r]);
                        acc[r] = ffma2(av.y, wreg[u].y, acc[r]);
                    }
                }
            }
            if (s2) {
                #pragma unroll
                for (int r = 0; r < 4; r++) partA[(head * 128 + jj) * 5 + r] = hsum2(acc[r]);
            }
            __syncthreads();   // S4
            if (!s2) {
                int tb = t * BATCH + r0;
                #pragma unroll
                for (int r = 0; r < 4; r++) {
                    float v = hsum2(acc[r]) + partA[(head * 128 + jj) * 5 + r] + bB;
                    size_t orow = (size_t)(tb + r) * LAT;
                    if (head) {
                        post_s[r][jj] = v;
                        if (jj < 64) out[OFF_POSTM  + orow + jj]      = v;
                        else         out[OFF_POSTLV + orow + jj - 64] = v;
                    } else {
                        if (jj < 64) out[OFF_PM  + orow + jj]      = v;
                        else         out[OFF_PLV + orow + jj - 64] = v;
                    }
                }
            }
        }
        __syncthreads();   // S5

        // ---- z update
        if (tid < 256) {
            int r = tid >> 6, lz = tid & 63;
            float pm  = post_s[r][lz];
            float plv = post_s[r][LAT + lz];
            pin_s[r][HID + lz] = pm + epv * __expf(0.5f * plv);
        }
        __syncthreads();   // S6

        // ---- Stage C: decoder hidden (K=64, split2) — one 8-deep block
        {
            #pragma unroll
            for (int u = 0; u < 8; u++) wreg[u] = dw1p[(s2 * 8 + u) * HID + j2];
            unsigned long long acc[4] = {0,0,0,0};
            #pragma unroll
            for (int u = 0; u < 8; u++) {
                int k4 = s2 * 8 + u;
                #pragma unroll
                for (int r = 0; r < 4; r++) {
                    ulonglong2 av = *(const ulonglong2*)&pin_s[r][HID + k4 * 4];
                    acc[r] = ffma2(av.x, wreg[u].x, acc[r]);
                    acc[r] = ffma2(av.y, wreg[u].y, acc[r]);
                }
            }
            if (s2) {
                #pragma unroll
                for (int r = 0; r < 4; r++) partB[j2 * 5 + r] = hsum2(acc[r]);
            }
            __syncthreads();   // S7
            if (!s2) {
                #pragma unroll
                for (int r = 0; r < 4; r++)
                    a1_s[r][j2] = fmaxf(hsum2(acc[r]) + partB[j2 * 5 + r] + db1_j, 0.f);
            }
        }
        __syncthreads();   // S8

        // ---- Stage D: recon (K=256, split4) — two 8-deep blocks
        {
            unsigned long long acc[4] = {0,0,0,0};
            for (int blk = 0; blk < 2; blk++) {
                int kb = sD * 16 + blk * 8;
                #pragma unroll
                for (int u = 0; u < 8; u++) wreg[u] = dw2p[(kb + u) * 128 + jj];
                #pragma unroll
                for (int u = 0; u < 8; u++) {
                    int k4 = kb + u;
                    #pragma unroll
                    for (int r = 0; r < 4; r++) {
                        ulonglong2 av = *(const ulonglong2*)&a1_s[r][k4 * 4];
                        acc[r] = ffma2(av.x, wreg[u].x, acc[r]);
                        acc[r] = ffma2(av.y, wreg[u].y, acc[r]);
                    }
                }
            }
            if (sD) {
                #pragma unroll
                for (int r = 0; r < 4; r++) partD[sD - 1][jj * 5 + r] = hsum2(acc[r]);
            }
            __syncthreads();   // S9
            if (sD == 0) {
                #pragma unroll
                for (int r = 0; r < 4; r++) {
                    float v = hsum2(acc[r]) + partD[0][jj * 5 + r] + partD[1][jj * 5 + r]
                            + partD[2][jj * 5 + r] + db2_j;
                    out[OFF_REC + ((size_t)t * BATCH + r0 + r) * OBS + jj] = v;
                }
            }
        }
        __syncthreads();   // S10
    }
}

// ---------------- host launch -------------------------------------------------
extern "C" void kernel_launch(void* const* d_in, const int* in_sizes, int n_in,
                              void* d_out, int out_size) {
    const float* x   = (const float*)d_in[0];
    const float* eps = (const float*)d_in[1];
    const float* Wih = (const float*)d_in[2];
    const float* Whh = (const float*)d_in[3];
    const float* bih = (const float*)d_in[4];
    const float* bhh = (const float*)d_in[5];
    const float* tW1 = (const float*)d_in[6];
    const float* tb1 = (const float*)d_in[7];
    const float* tW2 = (const float*)d_in[8];
    const float* tb2 = (const float*)d_in[9];
    const float* pW1 = (const float*)d_in[10];
    const float* pb1 = (const float*)d_in[11];
    const float* pW2 = (const float*)d_in[12];
    const float* pb2 = (const float*)d_in[13];
    const float* dW1 = (const float*)d_in[14];
    const float* db1 = (const float*)d_in[15];
    const float* dW2 = (const float*)d_in[16];
    const float* db2 = (const float*)d_in[17];
    float* out = (float*)d_out;

    static int smem_set = 0;
    if (!smem_set) {
        cudaFuncSetAttribute(gru_cluster_kernel,
                             cudaFuncAttributeMaxDynamicSharedMemorySize, GRU_SMEM_BYTES);
        smem_set = 1;
    }

    pack_all<<<64, 256>>>(tW1, tW2, pW1, pW2, dW1, dW2);

    dim3 g1(G3 / 64, (T_STEPS * BATCH) / 64);
    gx_kernel<<<g1, 256>>>(x, Wih, bih);

    gru_cluster_kernel<<<128, GRU_THREADS, GRU_SMEM_BYTES>>>(Whh, bhh);

    vrnn_kernel<<<64, 512>>>(eps, tb1, tb2, pb1, pb2, db1, db2, out);
}

// round 16
// speedup vs baseline: 2.3698x; 1.0571x over previous
#include <cuda_runtime.h>
#include <math.h>

#define T_STEPS 512
#define BATCH   256
#define OBS     128
#define LAT     64
#define HID     256
#define G3      (3*HID)
#define PIN     (HID+LAT)

__device__ __align__(16) float g_gx[(size_t)T_STEPS*BATCH*G3];
__device__ __align__(16) float g_hs[(size_t)T_STEPS*BATCH*HID];
__device__ __align__(16) float g_tw1_p[HID*LAT];
__device__ __align__(16) float g_tw2_p[2*LAT*HID];
__device__ __align__(16) float g_pw1_p[HID*PIN];
__device__ __align__(16) float g_pw2_p[2*LAT*HID];
__device__ __align__(16) float g_dw1_p[HID*LAT];
__device__ __align__(16) float g_dw2_p[OBS*HID];

#define OFF_REC    0
#define OFF_PM     ((size_t)T_STEPS*BATCH*OBS)
#define OFF_PLV    (OFF_PM  + (size_t)T_STEPS*BATCH*LAT)
#define OFF_POSTM  (OFF_PLV + (size_t)T_STEPS*BATCH*LAT)
#define OFF_POSTLV (OFF_POSTM + (size_t)T_STEPS*BATCH*LAT)

__device__ __forceinline__ unsigned long long ffma2(unsigned long long a,
                                                    unsigned long long b,
                                                    unsigned long long c) {
    unsigned long long d;
    asm("fma.rn.f32x2 %0, %1, %2, %3;" : "=l"(d) : "l"(a), "l"(b), "l"(c));
    return d;
}
__device__ __forceinline__ float hsum2(unsigned long long v) {
    float lo, hi;
    asm("mov.b64 {%0, %1}, %2;" : "=f"(lo), "=f"(hi) : "l"(v));
    return lo + hi;
}
__device__ __forceinline__ float fast_sigmoid(float x) {
    return __fdividef(1.f, 1.f + __expf(-x));
}
__device__ __forceinline__ float fast_tanh(float x) {
    return 1.f - __fdividef(2.f, __expf(2.f * x) + 1.f);
}
__device__ __forceinline__ unsigned smem_u32(const void* p) {
    unsigned a;
    asm("{ .reg .u64 t; cvta.to.shared.u64 t, %1; cvt.u32.u64 %0, t; }" : "=r"(a) : "l"(p));
    return a;
}
__device__ __forceinline__ void st_cluster_f32(unsigned addr, unsigned rank, float v) {
    asm volatile("{ .reg .b32 ra; mapa.shared::cluster.u32 ra, %0, %1; "
                 "st.shared::cluster.f32 [ra], %2; }"
                 :: "r"(addr), "r"(rank), "f"(v) : "memory");
}
__device__ __forceinline__ void cluster_sync_() {
    asm volatile("barrier.cluster.arrive.aligned;" ::: "memory");
    asm volatile("barrier.cluster.wait.aligned;" ::: "memory");
}
// butterfly reduce-scatter over the 8 lanes (bits 0-2): lane k8 ends with row k8 sum
__device__ __forceinline__ float reduce8(float* v, int k8) {
    #pragma unroll
    for (int m = 4; m >= 1; m >>= 1) {
        #pragma unroll
        for (int i = 0; i < m; i++) {
            float send = (k8 & m) ? v[i] : v[i + m];
            float got  = __shfl_xor_sync(0xffffffffu, send, m);
            v[i] = ((k8 & m) ? v[i + m] : v[i]) + got;
        }
    }
    return v[0];
}

__device__ __forceinline__ void pack_seg(const float* __restrict__ s,
                                         float* __restrict__ d,
                                         int nout, int kin, int tid, int stride) {
    int total = nout * kin;
    for (int idx = tid; idx < total; idx += stride) {
        int j = idx / kin;
        int k = idx - j * kin;
        d[((k >> 2) * nout + j) * 4 + (k & 3)] = s[idx];
    }
}
__global__ void pack_all(const float* __restrict__ tW1, const float* __restrict__ tW2,
                         const float* __restrict__ pW1, const float* __restrict__ pW2,
                         const float* __restrict__ dW1, const float* __restrict__ dW2) {
    int tid = blockIdx.x * blockDim.x + threadIdx.x;
    int stride = gridDim.x * blockDim.x;
    pack_seg(tW1, g_tw1_p, HID,   LAT, tid, stride);
    pack_seg(tW2, g_tw2_p, 2*LAT, HID, tid, stride);
    pack_seg(pW1, g_pw1_p, HID,   PIN, tid, stride);
    pack_seg(pW2, g_pw2_p, 2*LAT, HID, tid, stride);
    pack_seg(dW1, g_dw1_p, HID,   LAT, tid, stride);
    pack_seg(dW2, g_dw2_p, OBS,   HID, tid, stride);
}

__global__ void __launch_bounds__(256) gx_kernel(const float* __restrict__ x,
                                                 const float* __restrict__ Wih,
                                                 const float* __restrict__ bih) {
    __shared__ float xs[64][68];
    __shared__ float wsm[64][68];
    const int tid = threadIdx.x;
    const int ty = tid >> 4, tx = tid & 15;
    const int m0 = blockIdx.y * 64;
    const int n0 = blockIdx.x * 64;
    unsigned long long acc[4][4];
    #pragma unroll
    for (int i = 0; i < 4; i++)
        #pragma unroll
        for (int j = 0; j < 4; j++) acc[i][j] = 0ull;
    #pragma unroll
    for (int k0 = 0; k0 < OBS; k0 += 64) {
        #pragma unroll
        for (int p = 0; p < 4; p++) {
            int idx4 = tid + 256 * p;
            int row = idx4 >> 4;
            int c   = (idx4 & 15) * 4;
            *(float4*)&xs [row][c] = *(const float4*)&x  [(size_t)(m0 + row) * OBS + k0 + c];
            *(float4*)&wsm[row][c] = *(const float4*)&Wih[(size_t)(n0 + row) * OBS + k0 + c];
        }
        __syncthreads();
        #pragma unroll
        for (int k2 = 0; k2 < 32; k2++) {
            unsigned long long a[4], b[4];
            #pragma unroll
            for (int i = 0; i < 4; i++) a[i] = *(const unsigned long long*)&xs [ty + 16 * i][2 * k2];
            #pragma unroll
            for (int j = 0; j < 4; j++) b[j] = *(const unsigned long long*)&wsm[tx + 16 * j][2 * k2];
            #pragma unroll
            for (int i = 0; i < 4; i++)
                #pragma unroll
                for (int j = 0; j < 4; j++) acc[i][j] = ffma2(a[i], b[j], acc[i][j]);
        }
        __syncthreads();
    }
    #pragma unroll
    for (int i = 0; i < 4; i++) {
        int m = m0 + ty + 16 * i;
        #pragma unroll
        for (int j = 0; j < 4; j++) {
            int n = n0 + tx + 16 * j;
            g_gx[(size_t)m * G3 + n] = hsum2(acc[i][j]) + bih[n];
        }
    }
}

// -------- GRU scan (unchanged, working) --------------------------------------
#define GRU_THREADS   768
#define GRU_WS_FLOATS (64*192*4)
#define GRU_H_FLOATS  (2*8*256)
#define GRU_GH_FLOATS (8*192)
#define GRU_SMEM_BYTES ((GRU_WS_FLOATS + GRU_H_FLOATS + 3*GRU_GH_FLOATS)*4)

__global__ void __launch_bounds__(GRU_THREADS, 1) __cluster_dims__(4, 1, 1)
gru_cluster_kernel(const float* __restrict__ Whh, const float* __restrict__ bhh) {
    extern __shared__ float sm[];
    float* ws    = sm;
    float* hbuf  = ws + GRU_WS_FLOATS;
    float* gh    = hbuf + GRU_H_FLOATS;
    float* partA = gh + GRU_GH_FLOATS;
    float* partB = partA + GRU_GH_FLOATS;
    unsigned rank; asm("mov.u32 %0, %%cluster_ctarank;" : "=r"(rank));
    const int tid = threadIdx.x;
    const int r0  = (blockIdx.x >> 2) * 8;
    for (int idx = tid; idx < 192 * 64; idx += GRU_THREADS) {
        int k4 = idx / 192, l = idx - k4 * 192;
        int g = l >> 6, il = l & 63;
        int j = g * 256 + (int)rank * 64 + il;
        *(float4*)&ws[(size_t)idx * 4] = *(const float4*)&Whh[(size_t)j * 256 + k4 * 4];
    }
    for (int idx = tid; idx < GRU_H_FLOATS; idx += GRU_THREADS) hbuf[idx] = 0.f;
    const int l  = tid % 192;
    const int kq = tid / 192;
    const int gg = l >> 6, il = l & 63;
    const float bias = bhh[gg * 256 + (int)rank * 64 + il];
    const unsigned hbuf_u32 = smem_u32(hbuf);
    float* dst = (kq == 3) ? gh : ((kq == 2) ? partA : partB);
    __syncthreads();
    cluster_sync_();
    int buf = 0;
    for (int t = 0; t < T_STEPS; t++) {
        float gx0 = 0.f, gx1 = 0.f, gx2 = 0.f;
        if (tid < 512) {
            int r = tid >> 6, il2 = tid & 63;
            size_t base = ((size_t)t * BATCH + r0 + r) * G3 + rank * 64 + il2;
            gx0 = g_gx[base]; gx1 = g_gx[base + 256]; gx2 = g_gx[base + 512];
        }
        unsigned long long acc[8] = {0,0,0,0,0,0,0,0};
        const float* hb = hbuf + buf * 2048;
        #pragma unroll 4
        for (int kk = 0; kk < 16; kk++) {
            int k4 = kq * 16 + kk;
            ulonglong2 w = *(const ulonglong2*)&ws[(k4 * 192 + l) * 4];
            #pragma unroll
            for (int r = 0; r < 8; r++) {
                ulonglong2 hv = *(const ulonglong2*)&hb[r * 256 + k4 * 4];
                acc[r] = ffma2(hv.x, w.x, acc[r]);
                acc[r] = ffma2(hv.y, w.y, acc[r]);
            }
        }
        float v[8];
        #pragma unroll
        for (int r = 0; r < 8; r++) v[r] = hsum2(acc[r]);
        if (kq != 0) {
            #pragma unroll
            for (int r = 0; r < 8; r++) dst[r * 192 + l] = v[r];
        }
        __syncthreads();
        if (kq == 0) {
            #pragma unroll
            for (int r = 0; r < 8; r++)
                gh[r * 192 + l] = v[r] + gh[r * 192 + l] + partA[r * 192 + l]
                                + partB[r * 192 + l] + bias;
        }
        __syncthreads();
        if (tid < 512) {
            int r = tid >> 6, il2 = tid & 63;
            float hr_ = gh[r * 192 + il2];
            float hz_ = gh[r * 192 + 64 + il2];
            float hn_ = gh[r * 192 + 128 + il2];
            float rg = fast_sigmoid(gx0 + hr_);
            float zg = fast_sigmoid(gx1 + hz_);
            float ng = fast_tanh(gx2 + rg * hn_);
            float hold = hb[r * 256 + rank * 64 + il2];
            float hnew = (1.f - zg) * ng + zg * hold;
            unsigned off = (unsigned)(((buf ^ 1) * 2048 + r * 256 + (int)rank * 64 + il2) * 4);
            #pragma unroll
            for (int pr = 0; pr < 4; pr++) st_cluster_f32(hbuf_u32 + off, (unsigned)pr, hnew);
            g_hs[((size_t)t * BATCH + r0 + r) * HID + rank * 64 + il2] = hnew;
        }
        cluster_sync_();
        buf ^= 1;
    }
}

// -------- vrnn scan: 4-CTA clusters, weights SMEM/REG resident ---------------
#define VR_SMEM_FLOATS (20480 + 3*8192 + 2560 + 3*2048 + 1024)   // 54784
#define VR_SMEM_BYTES  (VR_SMEM_FLOATS*4)                         // 219136

__global__ void __launch_bounds__(512, 1) __cluster_dims__(4, 1, 1)
vrnn_cluster_kernel(const float* __restrict__ eps,
                    const float* __restrict__ tb1, const float* __restrict__ tb2,
                    const float* __restrict__ pb1, const float* __restrict__ pb2,
                    const float* __restrict__ db1, const float* __restrict__ db2,
                    float* __restrict__ out) {
    extern __shared__ float vs[];
    float* pw1s = vs;               // 20480  [(kk*64+j)*8+k8]*4
    float* tw2s = pw1s + 20480;     // 8192   [(kk*32+o)*8+k8]*4
    float* pw2s = tw2s + 8192;
    float* dw2s = pw2s + 8192;
    float* pin  = dw2s + 8192;      // [8][320]
    float* a1s  = pin + 2560;       // [8][256]
    float* a2s  = a1s + 2048;
    float* a3s  = a2s + 2048;
    float* posts= a3s + 2048;       // [8][128]

    unsigned rank; asm("mov.u32 %0, %%cluster_ctarank;" : "=r"(rank));
    const int tid = threadIdx.x;
    const int r0  = (blockIdx.x >> 2) * 8;
    const int j   = tid >> 3;       // 0..63
    const int k8  = tid & 7;

    // one-time SMEM weight slices (output-sliced by rank)
    for (int g = tid; g < 5120; g += 512) {
        int kk = g >> 9, rem = g & 511, jj = rem >> 3, kq = rem & 7;
        *(float4*)&pw1s[g * 4] =
            *(const float4*)&g_pw1_p[(((kk * 8 + kq) * 256) + 64 * (int)rank + jj) * 4];
    }
    for (int g = tid; g < 2048; g += 512) {
        int kk = g >> 8, rem = g & 255, o = rem >> 3, kq = rem & 7;
        int src = (((kk * 8 + kq) * 128) + 32 * (int)rank + o) * 4;
        *(float4*)&tw2s[g * 4] = *(const float4*)&g_tw2_p[src];
        *(float4*)&pw2s[g * 4] = *(const float4*)&g_pw2_p[src];
        *(float4*)&dw2s[g * 4] = *(const float4*)&g_dw2_p[src];
    }
    // register-resident tW1/dW1 slices (t-invariant)
    ulonglong2 tw1r[2], dw1r[2];
    #pragma unroll
    for (int kk = 0; kk < 2; kk++) {
        int k4 = kk * 8 + k8;
        tw1r[kk] = *(const ulonglong2*)&g_tw1_p[(k4 * 256 + 64 * (int)rank + j) * 4];
        dw1r[kk] = *(const ulonglong2*)&g_dw1_p[(k4 * 256 + 64 * (int)rank + j) * 4];
    }
    const float tb1_j = tb1[64 * (int)rank + j];
    const float pb1_j = pb1[64 * (int)rank + j];
    const float db1_j = db1[64 * (int)rank + j];
    const int   oB    = 32 * (int)rank + (j & 31);
    const float bB    = (j < 32) ? tb2[oB] : pb2[oB];
    const float db2_o = db2[32 * (int)rank + (j & 31)];
    { int r = tid >> 6, l = tid & 63; pin[r * 320 + 256 + l] = 0.f; }  // z0
    const unsigned a1u = smem_u32(a1s), a2u = smem_u32(a2s);
    const unsigned a3u = smem_u32(a3s), pou = smem_u32(posts);
    __syncthreads();
    cluster_sync_();

    for (int t = 0; t < T_STEPS; t++) {
        const int rr = tid >> 6, ll = tid & 63;
        float epv = eps[((size_t)t * BATCH + r0 + rr) * LAT + ll];
        *(float4*)&pin[rr * 320 + ll * 4] =
            *(const float4*)&g_hs[((size_t)t * BATCH + r0 + rr) * HID + ll * 4];
        __syncthreads();

        // Stage A: a1 slice (K=64 over z), tW1 in regs
        {
            unsigned long long acc[8] = {0,0,0,0,0,0,0,0};
            #pragma unroll
            for (int kk = 0; kk < 2; kk++) {
                int k4 = kk * 8 + k8;
                #pragma unroll
                for (int r = 0; r < 8; r++) {
                    ulonglong2 av = *(const ulonglong2*)&pin[r * 320 + 256 + k4 * 4];
                    acc[r] = ffma2(av.x, tw1r[kk].x, acc[r]);
                    acc[r] = ffma2(av.y, tw1r[kk].y, acc[r]);
                }
            }
            float v[8];
            #pragma unroll
            for (int r = 0; r < 8; r++) v[r] = hsum2(acc[r]);
            float a = fmaxf(reduce8(v, k8) + tb1_j, 0.f);
            unsigned off = (unsigned)((k8 * 256 + 64 * (int)rank + j) * 4);
            #pragma unroll
            for (unsigned d = 0; d < 4; d++) st_cluster_f32(a1u + off, d, a);
        }
        // Stage A2: a2 slice (K=320 over pin), pW1 in SMEM
        {
            unsigned long long acc[8] = {0,0,0,0,0,0,0,0};
            #pragma unroll
            for (int kk = 0; kk < 10; kk++) {
                int k4 = kk * 8 + k8;
                ulonglong2 w = *(const ulonglong2*)&pw1s[((kk * 64 + j) * 8 + k8) * 4];
                #pragma unroll
                for (int r = 0; r < 8; r++) {
                    ulonglong2 av = *(const ulonglong2*)&pin[r * 320 + k4 * 4];
                    acc[r] = ffma2(av.x, w.x, acc[r]);
                    acc[r] = ffma2(av.y, w.y, acc[r]);
                }
            }
            float v[8];
            #pragma unroll
            for (int r = 0; r < 8; r++) v[r] = hsum2(acc[r]);
            float a = fmaxf(reduce8(v, k8) + pb1_j, 0.f);
            unsigned off = (unsigned)((k8 * 256 + 64 * (int)rank + j) * 4);
            #pragma unroll
            for (unsigned d = 0; d < 4; d++) st_cluster_f32(a2u + off, d, a);
        }
        cluster_sync_();   // a1/a2 gathered cluster-wide

        // Stage B: heads (K=256). warps 0-7: prior (a1,tW2); warps 8-15: post (a2,pW2)
        {
            const int o = j & 31;
            const float* asrc = (j < 32) ? a1s : a2s;
            const float* wsb  = (j < 32) ? tw2s : pw2s;
            unsigned long long acc[8] = {0,0,0,0,0,0,0,0};
            #pragma unroll
            for (int kk = 0; kk < 8; kk++) {
                int k4 = kk * 8 + k8;
                ulonglong2 w = *(const ulonglong2*)&wsb[((kk * 32 + o) * 8 + k8) * 4];
                #pragma unroll
                for (int r = 0; r < 8; r++) {
                    ulonglong2 av = *(const ulonglong2*)&asrc[r * 256 + k4 * 4];
                    acc[r] = ffma2(av.x, w.x, acc[r]);
                    acc[r] = ffma2(av.y, w.y, acc[r]);
                }
            }
            float v[8];
            #pragma unroll
            for (int r = 0; r < 8; r++) v[r] = hsum2(acc[r]);
            float val = reduce8(v, k8) + bB;
            int jg = 32 * (int)rank + o;
            size_t orow = ((size_t)t * BATCH + r0 + k8) * LAT;
            if (j < 32) {
                if (jg < 64) out[OFF_PM  + orow + jg]      = val;
                else         out[OFF_PLV + orow + jg - 64] = val;
            } else {
                unsigned off = (unsigned)((k8 * 128 + jg) * 4);
                #pragma unroll
                for (unsigned d = 0; d < 4; d++) st_cluster_f32(pou + off, d, val);
                if (jg < 64) out[OFF_POSTM  + orow + jg]      = val;
                else         out[OFF_POSTLV + orow + jg - 64] = val;
            }
        }
        cluster_sync_();   // posts gathered

        // z update (local)
        {
            float pm  = posts[rr * 128 + ll];
            float plv = posts[rr * 128 + 64 + ll];
            pin[rr * 320 + 256 + ll] = pm + epv * __expf(0.5f * plv);
        }
        __syncthreads();

        // Stage C: a3 slice (K=64 over z), dW1 in regs
        {
            unsigned long long acc[8] = {0,0,0,0,0,0,0,0};
            #pragma unroll
            for (int kk = 0; kk < 2; kk++) {
                int k4 = kk * 8 + k8;
                #pragma unroll
                for (int r = 0; r < 8; r++) {
                    ulonglong2 av = *(const ulonglong2*)&pin[r * 320 + 256 + k4 * 4];
                    acc[r] = ffma2(av.x, dw1r[kk].x, acc[r]);
                    acc[r] = ffma2(av.y, dw1r[kk].y, acc[r]);
                }
            }
            float v[8];
            #pragma unroll
            for (int r = 0; r < 8; r++) v[r] = hsum2(acc[r]);
            float a = fmaxf(reduce8(v, k8) + db1_j, 0.f);
            unsigned off = (unsigned)((k8 * 256 + 64 * (int)rank + j) * 4);
            #pragma unroll
            for (unsigned d = 0; d < 4; d++) st_cluster_f32(a3u + off, d, a);
        }
        cluster_sync_();   // a3 gathered

        // Stage D: recon slice (32 obs outs, K=256) on warps 0-7
        if (tid < 256) {
            const int o = j;   // 0..31
            unsigned long long acc[8] = {0,0,0,0,0,0,0,0};
            #pragma unroll
            for (int kk = 0; kk < 8; kk++) {
                int k4 = kk * 8 + k8;
                ulonglong2 w = *(const ulonglong2*)&dw2s[((kk * 32 + o) * 8 + k8) * 4];
                #pragma unroll
                for (int r = 0; r < 8; r++) {
                    ulonglong2 av = *(const ulonglong2*)&a3s[r * 256 + k4 * 4];
                    acc[r] = ffma2(av.x, w.x, acc[r]);
                    acc[r] = ffma2(av.y, w.y, acc[r]);
                }
            }
            float v[8];
            #pragma unroll
            for (int r = 0; r < 8; r++) v[r] = hsum2(acc[r]);
            float val = reduce8(v, k8) + db2_o;
            out[OFF_REC + ((size_t)t * BATCH + r0 + k8) * OBS + 32 * (int)rank + o] = val;
        }
        cluster_sync_();   // all reads done before next step's gathers
    }
}

extern "C" void kernel_launch(void* const* d_in, const int* in_sizes, int n_in,
                              void* d_out, int out_size) {
    const float* x   = (const float*)d_in[0];
    const float* eps = (const float*)d_in[1];
    const float* Wih = (const float*)d_in[2];
    const float* Whh = (const float*)d_in[3];
    const float* bih = (const float*)d_in[4];
    const float* bhh = (const float*)d_in[5];
    const float* tW1 = (const float*)d_in[6];
    const float* tb1 = (const float*)d_in[7];
    const float* tW2 = (const float*)d_in[8];
    const float* tb2 = (const float*)d_in[9];
    const float* pW1 = (const float*)d_in[10];
    const float* pb1 = (const float*)d_in[11];
    const float* pW2 = (const float*)d_in[12];
    const float* pb2 = (const float*)d_in[13];
    const float* dW1 = (const float*)d_in[14];
    const float* db1 = (const float*)d_in[15];
    const float* dW2 = (const float*)d_in[16];
    const float* db2 = (const float*)d_in[17];
    float* out = (float*)d_out;

    static int smem_set = 0;
    if (!smem_set) {
        cudaFuncSetAttribute(gru_cluster_kernel,
                             cudaFuncAttributeMaxDynamicSharedMemorySize, GRU_SMEM_BYTES);
        cudaFuncSetAttribute(vrnn_cluster_kernel,
                             cudaFuncAttributeMaxDynamicSharedMemorySize, VR_SMEM_BYTES);
        smem_set = 1;
    }

    pack_all<<<64, 256>>>(tW1, tW2, pW1, pW2, dW1, dW2);
    dim3 g1(G3 / 64, (T_STEPS * BATCH) / 64);
    gx_kernel<<<g1, 256>>>(x, Wih, bih);
    gru_cluster_kernel<<<128, GRU_THREADS, GRU_SMEM_BYTES>>>(Whh, bhh);
    vrnn_cluster_kernel<<<128, 512, VR_SMEM_BYTES>>>(eps, tb1, tb2, pb1, pb2,
                                                     db1, db2, out);
}

// round 17
// speedup vs baseline: 3.0339x; 1.2802x over previous
#include <cuda_runtime.h>
#include <math.h>

#define T_STEPS 512
#define BATCH   256
#define OBS     128
#define LAT     64
#define HID     256
#define G3      (3*HID)
#define PIN     (HID+LAT)

__device__ __align__(16) float g_gx[(size_t)T_STEPS*BATCH*G3];
__device__ __align__(16) float g_hs[(size_t)T_STEPS*BATCH*HID];
__device__ __align__(16) float g_tw1_p[HID*LAT];
__device__ __align__(16) float g_tw2_p[2*LAT*HID];
__device__ __align__(16) float g_pw1_p[HID*PIN];
__device__ __align__(16) float g_pw2_p[2*LAT*HID];
__device__ __align__(16) float g_dw1_p[HID*LAT];
__device__ __align__(16) float g_dw2_p[OBS*HID];

#define OFF_REC    0
#define OFF_PM     ((size_t)T_STEPS*BATCH*OBS)
#define OFF_PLV    (OFF_PM  + (size_t)T_STEPS*BATCH*LAT)
#define OFF_POSTM  (OFF_PLV + (size_t)T_STEPS*BATCH*LAT)
#define OFF_POSTLV (OFF_POSTM + (size_t)T_STEPS*BATCH*LAT)

__device__ __forceinline__ unsigned long long ffma2(unsigned long long a,
                                                    unsigned long long b,
                                                    unsigned long long c) {
    unsigned long long d;
    asm("fma.rn.f32x2 %0, %1, %2, %3;" : "=l"(d) : "l"(a), "l"(b), "l"(c));
    return d;
}
__device__ __forceinline__ float hsum2(unsigned long long v) {
    float lo, hi;
    asm("mov.b64 {%0, %1}, %2;" : "=f"(lo), "=f"(hi) : "l"(v));
    return lo + hi;
}
__device__ __forceinline__ float fast_sigmoid(float x) {
    return __fdividef(1.f, 1.f + __expf(-x));
}
__device__ __forceinline__ float fast_tanh(float x) {
    return 1.f - __fdividef(2.f, __expf(2.f * x) + 1.f);
}
__device__ __forceinline__ unsigned smem_u32(const void* p) {
    unsigned a;
    asm("{ .reg .u64 t; cvta.to.shared.u64 t, %1; cvt.u32.u64 %0, t; }" : "=r"(a) : "l"(p));
    return a;
}
__device__ __forceinline__ void st_cluster_f32(unsigned addr, unsigned rank, float v) {
    asm volatile("{ .reg .b32 ra; mapa.shared::cluster.u32 ra, %0, %1; "
                 "st.shared::cluster.f32 [ra], %2; }"
                 :: "r"(addr), "r"(rank), "f"(v) : "memory");
}
__device__ __forceinline__ void gather4(unsigned addr, float v) {
    #pragma unroll
    for (unsigned d = 0; d < 4; d++) st_cluster_f32(addr, d, v);
}
__device__ __forceinline__ void cluster_sync_() {
    asm volatile("barrier.cluster.arrive.aligned;" ::: "memory");
    asm volatile("barrier.cluster.wait.aligned;" ::: "memory");
}

__device__ __forceinline__ void pack_seg(const float* __restrict__ s,
                                         float* __restrict__ d,
                                         int nout, int kin, int tid, int stride) {
    int total = nout * kin;
    for (int idx = tid; idx < total; idx += stride) {
        int j = idx / kin;
        int k = idx - j * kin;
        d[((k >> 2) * nout + j) * 4 + (k & 3)] = s[idx];
    }
}
__global__ void pack_all(const float* __restrict__ tW1, const float* __restrict__ tW2,
                         const float* __restrict__ pW1, const float* __restrict__ pW2,
                         const float* __restrict__ dW1, const float* __restrict__ dW2) {
    int tid = blockIdx.x * blockDim.x + threadIdx.x;
    int stride = gridDim.x * blockDim.x;
    pack_seg(tW1, g_tw1_p, HID,   LAT, tid, stride);
    pack_seg(tW2, g_tw2_p, 2*LAT, HID, tid, stride);
    pack_seg(pW1, g_pw1_p, HID,   PIN, tid, stride);
    pack_seg(pW2, g_pw2_p, 2*LAT, HID, tid, stride);
    pack_seg(dW1, g_dw1_p, HID,   LAT, tid, stride);
    pack_seg(dW2, g_dw2_p, OBS,   HID, tid, stride);
}

__global__ void __launch_bounds__(256) gx_kernel(const float* __restrict__ x,
                                                 const float* __restrict__ Wih,
                                                 const float* __restrict__ bih) {
    __shared__ float xs[64][68];
    __shared__ float wsm[64][68];
    const int tid = threadIdx.x;
    const int ty = tid >> 4, tx = tid & 15;
    const int m0 = blockIdx.y * 64;
    const int n0 = blockIdx.x * 64;
    unsigned long long acc[4][4];
    #pragma unroll
    for (int i = 0; i < 4; i++)
        #pragma unroll
        for (int j = 0; j < 4; j++) acc[i][j] = 0ull;
    #pragma unroll
    for (int k0 = 0; k0 < OBS; k0 += 64) {
        #pragma unroll
        for (int p = 0; p < 4; p++) {
            int idx4 = tid + 256 * p;
            int row = idx4 >> 4;
            int c   = (idx4 & 15) * 4;
            *(float4*)&xs [row][c] = *(const float4*)&x  [(size_t)(m0 + row) * OBS + k0 + c];
            *(float4*)&wsm[row][c] = *(const float4*)&Wih[(size_t)(n0 + row) * OBS + k0 + c];
        }
        __syncthreads();
        #pragma unroll
        for (int k2 = 0; k2 < 32; k2++) {
            unsigned long long a[4], b[4];
            #pragma unroll
            for (int i = 0; i < 4; i++) a[i] = *(const unsigned long long*)&xs [ty + 16 * i][2 * k2];
            #pragma unroll
            for (int j = 0; j < 4; j++) b[j] = *(const unsigned long long*)&wsm[tx + 16 * j][2 * k2];
            #pragma unroll
            for (int i = 0; i < 4; i++)
                #pragma unroll
                for (int j = 0; j < 4; j++) acc[i][j] = ffma2(a[i], b[j], acc[i][j]);
        }
        __syncthreads();
    }
    #pragma unroll
    for (int i = 0; i < 4; i++) {
        int m = m0 + ty + 16 * i;
        #pragma unroll
        for (int j = 0; j < 4; j++) {
            int n = n0 + tx + 16 * j;
            g_gx[(size_t)m * G3 + n] = hsum2(acc[i][j]) + bih[n];
        }
    }
}

// -------- GRU scan (unchanged, working) --------------------------------------
#define GRU_THREADS   768
#define GRU_WS_FLOATS (64*192*4)
#define GRU_H_FLOATS  (2*8*256)
#define GRU_GH_FLOATS (8*192)
#define GRU_SMEM_BYTES ((GRU_WS_FLOATS + GRU_H_FLOATS + 3*GRU_GH_FLOATS)*4)

__global__ void __launch_bounds__(GRU_THREADS, 1) __cluster_dims__(4, 1, 1)
gru_cluster_kernel(const float* __restrict__ Whh, const float* __restrict__ bhh) {
    extern __shared__ float sm[];
    float* ws    = sm;
    float* hbuf  = ws + GRU_WS_FLOATS;
    float* gh    = hbuf + GRU_H_FLOATS;
    float* partA = gh + GRU_GH_FLOATS;
    float* partB = partA + GRU_GH_FLOATS;
    unsigned rank; asm("mov.u32 %0, %%cluster_ctarank;" : "=r"(rank));
    const int tid = threadIdx.x;
    const int r0  = (blockIdx.x >> 2) * 8;
    for (int idx = tid; idx < 192 * 64; idx += GRU_THREADS) {
        int k4 = idx / 192, l = idx - k4 * 192;
        int g = l >> 6, il = l & 63;
        int j = g * 256 + (int)rank * 64 + il;
        *(float4*)&ws[(size_t)idx * 4] = *(const float4*)&Whh[(size_t)j * 256 + k4 * 4];
    }
    for (int idx = tid; idx < GRU_H_FLOATS; idx += GRU_THREADS) hbuf[idx] = 0.f;
    const int l  = tid % 192;
    const int kq = tid / 192;
    const int gg = l >> 6, il = l & 63;
    const float bias = bhh[gg * 256 + (int)rank * 64 + il];
    const unsigned hbuf_u32 = smem_u32(hbuf);
    float* dst = (kq == 3) ? gh : ((kq == 2) ? partA : partB);
    __syncthreads();
    cluster_sync_();
    int buf = 0;
    for (int t = 0; t < T_STEPS; t++) {
        float gx0 = 0.f, gx1 = 0.f, gx2 = 0.f;
        if (tid < 512) {
            int r = tid >> 6, il2 = tid & 63;
            size_t base = ((size_t)t * BATCH + r0 + r) * G3 + rank * 64 + il2;
            gx0 = g_gx[base]; gx1 = g_gx[base + 256]; gx2 = g_gx[base + 512];
        }
        unsigned long long acc[8] = {0,0,0,0,0,0,0,0};
        const float* hb = hbuf + buf * 2048;
        #pragma unroll 4
        for (int kk = 0; kk < 16; kk++) {
            int k4 = kq * 16 + kk;
            ulonglong2 w = *(const ulonglong2*)&ws[(k4 * 192 + l) * 4];
            #pragma unroll
            for (int r = 0; r < 8; r++) {
                ulonglong2 hv = *(const ulonglong2*)&hb[r * 256 + k4 * 4];
                acc[r] = ffma2(hv.x, w.x, acc[r]);
                acc[r] = ffma2(hv.y, w.y, acc[r]);
            }
        }
        float v[8];
        #pragma unroll
        for (int r = 0; r < 8; r++) v[r] = hsum2(acc[r]);
        if (kq != 0) {
            #pragma unroll
            for (int r = 0; r < 8; r++) dst[r * 192 + l] = v[r];
        }
        __syncthreads();
        if (kq == 0) {
            #pragma unroll
            for (int r = 0; r < 8; r++)
                gh[r * 192 + l] = v[r] + gh[r * 192 + l] + partA[r * 192 + l]
                                + partB[r * 192 + l] + bias;
        }
        __syncthreads();
        if (tid < 512) {
            int r = tid >> 6, il2 = tid & 63;
            float hr_ = gh[r * 192 + il2];
            float hz_ = gh[r * 192 + 64 + il2];
            float hn_ = gh[r * 192 + 128 + il2];
            float rg = fast_sigmoid(gx0 + hr_);
            float zg = fast_sigmoid(gx1 + hz_);
            float ng = fast_tanh(gx2 + rg * hn_);
            float hold = hb[r * 256 + rank * 64 + il2];
            float hnew = (1.f - zg) * ng + zg * hold;
            unsigned off = (unsigned)(((buf ^ 1) * 2048 + r * 256 + (int)rank * 64 + il2) * 4);
            #pragma unroll
            for (int pr = 0; pr < 4; pr++) st_cluster_f32(hbuf_u32 + off, (unsigned)pr, hnew);
            g_hs[((size_t)t * BATCH + r0 + r) * HID + rank * 64 + il2] = hnew;
        }
        cluster_sync_();
        buf ^= 1;
    }
}

// -------- vrnn scan: j-major warps, cross-warp k-split, conflict-free gathers -
// SMEM float offsets
#define VR_TW2S 20480
#define VR_PW2S (VR_TW2S+8192)
#define VR_DW2S (VR_PW2S+8192)
#define VR_PIN  (VR_DW2S+8192)
#define VR_A1   (VR_PIN+2560)
#define VR_A2   (VR_A1+2048)
#define VR_PO   (VR_A2+2048)
#define VR_PART (VR_PO+1024)
#define VR_FLOATS (VR_PART+4608)
#define VR_SMEM_BYTES (VR_FLOATS*4)    // 229376

__global__ void __launch_bounds__(512, 1) __cluster_dims__(4, 1, 1)
vrnn_cluster_kernel(const float* __restrict__ eps,
                    const float* __restrict__ tb1, const float* __restrict__ tb2,
                    const float* __restrict__ pb1, const float* __restrict__ pb2,
                    const float* __restrict__ db1, const float* __restrict__ db2,
                    float* __restrict__ out) {
    extern __shared__ float vs[];
    float* pw1s = vs;                 // [k4 0..79][j 0..63]*4
    float* tw2s = vs + VR_TW2S;       // [k4 0..63][o 0..31]*4
    float* pw2s = vs + VR_PW2S;
    float* dw2s = vs + VR_DW2S;
    float* pin  = vs + VR_PIN;        // [8][320] = [h|z]
    float* a1s  = vs + VR_A1;         // [8][256]   (also a3)
    float* a2s  = vs + VR_A2;         // [8][256]
    float* posts= vs + VR_PO;         // [8][128]
    float* part = vs + VR_PART;       // [(r*64+q)*9 + ks]

    unsigned rank; asm("mov.u32 %0, %%cluster_ctarank;" : "=r"(rank));
    const int tid  = threadIdx.x;
    const int r0   = (blockIdx.x >> 2) * 8;
    const int lane = tid & 31;
    const int ks   = tid >> 5;        // warp id; GEMV warps: ks 0..7
    const int qq   = tid & 63;        // reduce mapping: out index
    const int qr   = tid >> 6;        // reduce mapping: row

    // SMEM weight slices
    for (int i = tid; i < 5120; i += 512) {
        int k4 = i >> 6, j = i & 63;
        *(float4*)&pw1s[i * 4] =
            *(const float4*)&g_pw1_p[(size_t)(k4 * 256 + 64 * (int)rank + j) * 4];
    }
    for (int i = tid; i < 2048; i += 512) {
        int k4 = i >> 5, o = i & 31;
        int src = (k4 * 128 + 32 * (int)rank + o) * 4;
        *(float4*)&tw2s[i * 4] = *(const float4*)&g_tw2_p[src];
        *(float4*)&pw2s[i * 4] = *(const float4*)&g_pw2_p[src];
        *(float4*)&dw2s[i * 4] = *(const float4*)&g_dw2_p[src];
    }
    // reg weights for stages A/C (valid for GEMV threads; harmless otherwise)
    ulonglong2 tw1r[2][2], dw1r[2][2];
    {
        int kse = ks & 7;
        #pragma unroll
        for (int c = 0; c < 2; c++)
            #pragma unroll
            for (int kk = 0; kk < 2; kk++) {
                int k4 = kse * 2 + kk;
                size_t off = (size_t)(k4 * 256 + 64 * (int)rank + lane + 32 * c) * 4;
                tw1r[c][kk] = *(const ulonglong2*)&g_tw1_p[off];
                dw1r[c][kk] = *(const ulonglong2*)&g_dw1_p[off];
            }
    }
    // biases for reduce threads
    const float tb1v = tb1[64 * (int)rank + qq];
    const float pb1v = pb1[64 * (int)rank + qq];
    const float db1v = db1[64 * (int)rank + qq];
    const int   bh   = qq >> 5, bo = qq & 31;
    const int   jgB  = 32 * (int)rank + bo;
    const float bBv  = bh ? pb2[jgB] : tb2[jgB];
    const float db2v = db2[32 * (int)rank + (tid & 31)];
    pin[qr * 320 + 256 + qq] = 0.f;   // z0
    const unsigned a1u = smem_u32(a1s), a2u = smem_u32(a2s), pou = smem_u32(posts);
    __syncthreads();
    cluster_sync_();

    const bool gv = (tid < 256);
    // stage-B constants for GEMV threads: head, output pair (q1,q1+16)
    const int bhp = lane >> 4;
    const int bol = lane & 15;
    const float* wBb = bhp ? pw2s : tw2s;
    const float* aBb = bhp ? a2s : a1s;
    const int q1B = bhp * 32 + bol;

    for (int t = 0; t < T_STEPS; t++) {
        float epv = eps[((size_t)t * BATCH + r0 + qr) * LAT + qq];
        *(float4*)&pin[qr * 320 + qq * 4] =
            *(const float4*)&g_hs[((size_t)t * BATCH + r0 + qr) * HID + qq * 4];
        __syncthreads();

        // ---- Stage A GEMV (K=64 over z, tW1 in regs)
        if (gv) {
            unsigned long long a0[8] = {0,0,0,0,0,0,0,0}, a1a[8] = {0,0,0,0,0,0,0,0};
            #pragma unroll
            for (int kk = 0; kk < 2; kk++) {
                int k4 = ks * 2 + kk;
                #pragma unroll
                for (int r = 0; r < 8; r++) {
                    ulonglong2 av = *(const ulonglong2*)&pin[r * 320 + 256 + k4 * 4];
                    a0[r]  = ffma2(av.x, tw1r[0][kk].x, a0[r]);
                    a0[r]  = ffma2(av.y, tw1r[0][kk].y, a0[r]);
                    a1a[r] = ffma2(av.x, tw1r[1][kk].x, a1a[r]);
                    a1a[r] = ffma2(av.y, tw1r[1][kk].y, a1a[r]);
                }
            }
            #pragma unroll
            for (int r = 0; r < 8; r++) {
                part[(r * 64 + lane) * 9 + ks]      = hsum2(a0[r]);
                part[(r * 64 + lane + 32) * 9 + ks] = hsum2(a1a[r]);
            }
        }
        __syncthreads();
        {
            float s = 0.f;
            #pragma unroll
            for (int k = 0; k < 8; k++) s += part[(qr * 64 + qq) * 9 + k];
            float a = fmaxf(s + tb1v, 0.f);
            gather4(a1u + (unsigned)((qr * 256 + 64 * (int)rank + qq) * 4), a);
        }
        __syncthreads();

        // ---- Stage A2 GEMV (K=320 over pin, pW1 in SMEM)
        if (gv) {
            unsigned long long a0[8] = {0,0,0,0,0,0,0,0}, a1a[8] = {0,0,0,0,0,0,0,0};
            #pragma unroll
            for (int kk = 0; kk < 10; kk++) {
                int k4 = ks * 10 + kk;
                ulonglong2 w1 = *(const ulonglong2*)&pw1s[(k4 * 64 + lane) * 4];
                ulonglong2 w2 = *(const ulonglong2*)&pw1s[(k4 * 64 + lane + 32) * 4];
                #pragma unroll
                for (int r = 0; r < 8; r++) {
                    ulonglong2 av = *(const ulonglong2*)&pin[r * 320 + k4 * 4];
                    a0[r]  = ffma2(av.x, w1.x, a0[r]);  a0[r]  = ffma2(av.y, w1.y, a0[r]);
                    a1a[r] = ffma2(av.x, w2.x, a1a[r]); a1a[r] = ffma2(av.y, w2.y, a1a[r]);
                }
            }
            #pragma unroll
            for (int r = 0; r < 8; r++) {
                part[(r * 64 + lane) * 9 + ks]      = hsum2(a0[r]);
                part[(r * 64 + lane + 32) * 9 + ks] = hsum2(a1a[r]);
            }
        }
        __syncthreads();
        {
            float s = 0.f;
            #pragma unroll
            for (int k = 0; k < 8; k++) s += part[(qr * 64 + qq) * 9 + k];
            float a = fmaxf(s + pb1v, 0.f);
            gather4(a2u + (unsigned)((qr * 256 + 64 * (int)rank + qq) * 4), a);
        }
        cluster_sync_();   // a1/a2 visible cluster-wide

        // ---- Stage B GEMV (K=256; lane head: prior or post; outputs q1B, q1B+16)
        if (gv) {
            unsigned long long a0[8] = {0,0,0,0,0,0,0,0}, a1a[8] = {0,0,0,0,0,0,0,0};
            #pragma unroll
            for (int kk = 0; kk < 8; kk++) {
                int k4 = ks * 8 + kk;
                ulonglong2 w1 = *(const ulonglong2*)&wBb[(k4 * 32 + bol) * 4];
                ulonglong2 w2 = *(const ulonglong2*)&wBb[(k4 * 32 + bol + 16) * 4];
                #pragma unroll
                for (int r = 0; r < 8; r++) {
                    ulonglong2 av = *(const ulonglong2*)&aBb[r * 256 + k4 * 4];
                    a0[r]  = ffma2(av.x, w1.x, a0[r]);  a0[r]  = ffma2(av.y, w1.y, a0[r]);
                    a1a[r] = ffma2(av.x, w2.x, a1a[r]); a1a[r] = ffma2(av.y, w2.y, a1a[r]);
                }
            }
            #pragma unroll
            for (int r = 0; r < 8; r++) {
                part[(r * 64 + q1B) * 9 + ks]      = hsum2(a0[r]);
                part[(r * 64 + q1B + 16) * 9 + ks] = hsum2(a1a[r]);
            }
        }
        __syncthreads();
        {
            float s = 0.f;
            #pragma unroll
            for (int k = 0; k < 8; k++) s += part[(qr * 64 + qq) * 9 + k];
            float val = s + bBv;
            size_t orow = ((size_t)t * BATCH + r0 + qr) * LAT;
            if (!bh) {
                if (jgB < 64) out[OFF_PM  + orow + jgB]      = val;
                else          out[OFF_PLV + orow + jgB - 64] = val;
            } else {
                gather4(pou + (unsigned)((qr * 128 + jgB) * 4), val);
                if (jgB < 64) out[OFF_POSTM  + orow + jgB]      = val;
                else          out[OFF_POSTLV + orow + jgB - 64] = val;
            }
        }
        cluster_sync_();   // posts visible

        // ---- z update
        {
            float pm  = posts[qr * 128 + qq];
            float plv = posts[qr * 128 + 64 + qq];
            pin[qr * 320 + 256 + qq] = pm + epv * __expf(0.5f * plv);
        }
        __syncthreads();

        // ---- Stage C GEMV (K=64 over z, dW1 in regs) -> a3 (into a1s)
        if (gv) {
            unsigned long long a0[8] = {0,0,0,0,0,0,0,0}, a1a[8] = {0,0,0,0,0,0,0,0};
            #pragma unroll
            for (int kk = 0; kk < 2; kk++) {
                int k4 = ks * 2 + kk;
                #pragma unroll
                for (int r = 0; r < 8; r++) {
                    ulonglong2 av = *(const ulonglong2*)&pin[r * 320 + 256 + k4 * 4];
                    a0[r]  = ffma2(av.x, dw1r[0][kk].x, a0[r]);
                    a0[r]  = ffma2(av.y, dw1r[0][kk].y, a0[r]);
                    a1a[r] = ffma2(av.x, dw1r[1][kk].x, a1a[r]);
                    a1a[r] = ffma2(av.y, dw1r[1][kk].y, a1a[r]);
                }
            }
            #pragma unroll
            for (int r = 0; r < 8; r++) {
                part[(r * 64 + lane) * 9 + ks]      = hsum2(a0[r]);
                part[(r * 64 + lane + 32) * 9 + ks] = hsum2(a1a[r]);
            }
        }
        __syncthreads();
        {
            float s = 0.f;
            #pragma unroll
            for (int k = 0; k < 8; k++) s += part[(qr * 64 + qq) * 9 + k];
            float a = fmaxf(s + db1v, 0.f);
            gather4(a1u + (unsigned)((qr * 256 + 64 * (int)rank + qq) * 4), a);
        }
        cluster_sync_();   // a3 visible

        // ---- Stage D GEMV (K=256, 32 outs, o = lane)
        if (gv) {
            unsigned long long a0[8] = {0,0,0,0,0,0,0,0};
            #pragma unroll
            for (int kk = 0; kk < 8; kk++) {
                int k4 = ks * 8 + kk;
                ulonglong2 w = *(const ulonglong2*)&dw2s[(k4 * 32 + lane) * 4];
                #pragma unroll
                for (int r = 0; r < 8; r++) {
                    ulonglong2 av = *(const ulonglong2*)&a1s[r * 256 + k4 * 4];
                    a0[r] = ffma2(av.x, w.x, a0[r]);
                    a0[r] = ffma2(av.y, w.y, a0[r]);
                }
            }
            #pragma unroll
            for (int r = 0; r < 8; r++)
                part[(r * 64 + lane) * 9 + ks] = hsum2(a0[r]);
        }
        __syncthreads();
        if (tid < 256) {
            int o = tid & 31, r = tid >> 5;
            float s = 0.f;
            #pragma unroll
            for (int k = 0; k < 8; k++) s += part[(r * 64 + o) * 9 + k];
            out[OFF_REC + ((size_t)t * BATCH + r0 + r) * OBS + 32 * (int)rank + o] = s + db2v;
        }
        cluster_sync_();   // a1s reads done before next-step gathers
    }
}

extern "C" void kernel_launch(void* const* d_in, const int* in_sizes, int n_in,
                              void* d_out, int out_size) {
    const float* x   = (const float*)d_in[0];
    const float* eps = (const float*)d_in[1];
    const float* Wih = (const float*)d_in[2];
    const float* Whh = (const float*)d_in[3];
    const float* bih = (const float*)d_in[4];
    const float* bhh = (const float*)d_in[5];
    const float* tW1 = (const float*)d_in[6];
    const float* tb1 = (const float*)d_in[7];
    const float* tW2 = (const float*)d_in[8];
    const float* tb2 = (const float*)d_in[9];
    const float* pW1 = (const float*)d_in[10];
    const float* pb1 = (const float*)d_in[11];
    const float* pW2 = (const float*)d_in[12];
    const float* pb2 = (const float*)d_in[13];
    const float* dW1 = (const float*)d_in[14];
    const float* db1 = (const float*)d_in[15];
    const float* dW2 = (const float*)d_in[16];
    const float* db2 = (const float*)d_in[17];
    float* out = (float*)d_out;

    static int smem_set = 0;
    if (!smem_set) {
        cudaFuncSetAttribute(gru_cluster_kernel,
                             cudaFuncAttributeMaxDynamicSharedMemorySize, GRU_SMEM_BYTES);
        cudaFuncSetAttribute(vrnn_cluster_kernel,
                             cudaFuncAttributeMaxDynamicSharedMemorySize, VR_SMEM_BYTES);
        smem_set = 1;
    }

    pack_all<<<64, 256>>>(tW1, tW2, pW1, pW2, dW1, dW2);
    dim3 g1(G3 / 64, (T_STEPS * BATCH) / 64);
    gx_kernel<<<g1, 256>>>(x, Wih, bih);
    gru_cluster_kernel<<<128, GRU_THREADS, GRU_SMEM_BYTES>>>(Whh, bhh);
    vrnn_cluster_kernel<<<128, 512, VR_SMEM_BYTES>>>(eps, tb1, tb2, pb1, pb2,
                                                     db1, db2, out);
}